// round 1
// baseline (speedup 1.0000x reference)
#include <cuda_runtime.h>
#include <math.h>

// ======================= scratch (static device memory) =======================
__device__ float g_adj [512*512];
__device__ float g_pqc [96];
__device__ float g_xa  [4096*512];
__device__ float g_oe  [4096*512];
__device__ float g_gt  [4096*512];
__device__ float g_xg  [4096*512];
__device__ float g_gw  [4096*512];
__device__ float g_h   [2*4*1024*512];
__device__ float g_c   [2*4*1024*512];
__device__ float g_z   [2*1024*2560];
__device__ float g_ycat[4096*1024];
__device__ float g_qkv [4096*3072];
__device__ float g_att [4096*1024];
__device__ float g_proj[4096*1024];
__device__ float g_y1  [4096*1024];
__device__ float g_milz[4096*1024];
__device__ float g_zln [4096*1024];
__device__ float g_dfc [1024*7];
__device__ float g_dxf [1024*1024];

// ======================= block reduction helpers =======================
__device__ __forceinline__ float blkSum(float v, float* sh) {
    int tid = threadIdx.x;
    #pragma unroll
    for (int o = 16; o > 0; o >>= 1) v += __shfl_down_sync(0xffffffffu, v, o);
    __syncthreads();
    if ((tid & 31) == 0) sh[tid >> 5] = v;
    __syncthreads();
    if (tid < 32) {
        float x = (tid < ((int)blockDim.x >> 5)) ? sh[tid] : 0.f;
        #pragma unroll
        for (int o = 16; o > 0; o >>= 1) x += __shfl_down_sync(0xffffffffu, x, o);
        if (tid == 0) sh[0] = x;
    }
    __syncthreads();
    return sh[0];
}

__device__ __forceinline__ float blkMax(float v, float* sh) {
    int tid = threadIdx.x;
    #pragma unroll
    for (int o = 16; o > 0; o >>= 1) v = fmaxf(v, __shfl_down_sync(0xffffffffu, v, o));
    __syncthreads();
    if ((tid & 31) == 0) sh[tid >> 5] = v;
    __syncthreads();
    if (tid < 32) {
        float x = (tid < ((int)blockDim.x >> 5)) ? sh[tid] : -3.4e38f;
        #pragma unroll
        for (int o = 16; o > 0; o >>= 1) x = fmaxf(x, __shfl_down_sync(0xffffffffu, x, o));
        if (tid == 0) sh[0] = x;
    }
    __syncthreads();
    return sh[0];
}

// ======================= adjacency: a[v,w] = (softmax(relu(nv1@nv2))[v,w] + I)/2 =======================
__global__ void adj_kernel(const float* __restrict__ nv1, const float* __restrict__ nv2,
                           float* __restrict__ a) {
    __shared__ float n1[32];
    __shared__ float row[512];
    __shared__ float sh[32];
    int v = blockIdx.x, tid = threadIdx.x;  // 128 threads
    if (tid < 32) n1[tid] = nv1[v * 32 + tid];
    __syncthreads();
    float mx = -3.4e38f;
    #pragma unroll
    for (int i = 0; i < 4; i++) {
        int j = i * 128 + tid;
        float r = 0.f;
        #pragma unroll
        for (int k = 0; k < 32; k++) r += n1[k] * nv2[k * 512 + j];
        r = fmaxf(r, 0.f);
        row[j] = r;
        mx = fmaxf(mx, r);
    }
    mx = blkMax(mx, sh);
    float ssum = 0.f;
    #pragma unroll
    for (int i = 0; i < 4; i++) {
        int j = i * 128 + tid;
        float e = expf(row[j] - mx);
        row[j] = e;
        ssum += e;
    }
    ssum = blkSum(ssum, sh);
    float inv = 1.f / ssum;
    #pragma unroll
    for (int i = 0; i < 4; i++) {
        int j = i * 128 + tid;
        a[v * 512 + j] = (row[j] * inv + (j == v ? 1.f : 0.f)) * 0.5f;
    }
}

// ======================= P/Q/C precompute (graph mlp collapse) =======================
__global__ void pqc_kernel(const float* __restrict__ mp_w, const float* __restrict__ mp_b,
                           const float* __restrict__ sc_w, const float* __restrict__ sc_b,
                           float* __restrict__ pqc) {
    int o = threadIdx.x;  // 32
    float a1 = 0.f, a2 = 0.f, cc = 0.f;
    for (int c = 0; c < 32; c++) {
        float w1 = mp_w[o * 64 + c], w2 = mp_w[o * 64 + 32 + c];
        a1 += w1 * sc_w[c];
        a2 += w2 * sc_w[c];
        cc += (w1 + w2) * sc_b[c];
    }
    cc += mp_b[o];
    pqc[o]      = a1 + 0.7f * a2;
    pqc[32 + o] = 0.3f * a2;
    pqc[64 + o] = cc;
}

// ======================= generic SGEMM: C = A@B^T (+bias), dual A/B split on K =======================
struct GemmP {
    const float *A1, *A2, *B1, *B2, *bias1, *bias2;
    float* C;
    int lda1, lda2, ldb1, ldb2, ldc;
};

__global__ void __launch_bounds__(256, 2)
sgemm_kernel(GemmP pa, GemmP pb, int M, int N, int K, int ksplit) {
    GemmP p = (blockIdx.z == 0) ? pa : pb;
    __shared__ float As[8][128];
    __shared__ float Bs[8][128];
    const int tid  = threadIdx.x;
    const int bm   = blockIdx.y * 128;
    const int bn   = blockIdx.x * 128;
    const int lrow = tid >> 1;
    const int lk   = (tid & 1) << 2;
    const int tr   = (tid >> 4) << 2;
    const int tc   = (tid & 15) << 2;

    float acc[8][8];
    #pragma unroll
    for (int i = 0; i < 8; i++)
        #pragma unroll
        for (int j = 0; j < 8; j++) acc[i][j] = 0.f;

    const int KT = K >> 3;
    float4 ra, rb;
    {
        int kg = lk;
        ra = (kg < ksplit)
                 ? *(const float4*)(p.A1 + (size_t)(bm + lrow) * p.lda1 + kg)
                 : *(const float4*)(p.A2 + (size_t)(bm + lrow) * p.lda2 + (kg - ksplit));
        rb = (kg < ksplit)
                 ? *(const float4*)(p.B1 + (size_t)(bn + lrow) * p.ldb1 + kg)
                 : *(const float4*)(p.B2 + (size_t)(bn + lrow) * p.ldb2 + (kg - ksplit));
    }
    for (int kt = 0; kt < KT; ++kt) {
        As[lk + 0][lrow] = ra.x; As[lk + 1][lrow] = ra.y;
        As[lk + 2][lrow] = ra.z; As[lk + 3][lrow] = ra.w;
        Bs[lk + 0][lrow] = rb.x; Bs[lk + 1][lrow] = rb.y;
        Bs[lk + 2][lrow] = rb.z; Bs[lk + 3][lrow] = rb.w;
        __syncthreads();
        if (kt + 1 < KT) {
            int kg = ((kt + 1) << 3) + lk;
            ra = (kg < ksplit)
                     ? *(const float4*)(p.A1 + (size_t)(bm + lrow) * p.lda1 + kg)
                     : *(const float4*)(p.A2 + (size_t)(bm + lrow) * p.lda2 + (kg - ksplit));
            rb = (kg < ksplit)
                     ? *(const float4*)(p.B1 + (size_t)(bn + lrow) * p.ldb1 + kg)
                     : *(const float4*)(p.B2 + (size_t)(bn + lrow) * p.ldb2 + (kg - ksplit));
        }
        #pragma unroll
        for (int k = 0; k < 8; k++) {
            float4 a0 = *(const float4*)&As[k][tr];
            float4 a1 = *(const float4*)&As[k][tr + 64];
            float4 b0 = *(const float4*)&Bs[k][tc];
            float4 b1 = *(const float4*)&Bs[k][tc + 64];
            float av[8] = {a0.x, a0.y, a0.z, a0.w, a1.x, a1.y, a1.z, a1.w};
            float bv[8] = {b0.x, b0.y, b0.z, b0.w, b1.x, b1.y, b1.z, b1.w};
            #pragma unroll
            for (int i = 0; i < 8; i++)
                #pragma unroll
                for (int j = 0; j < 8; j++) acc[i][j] += av[i] * bv[j];
        }
        __syncthreads();
    }
    float bb[8];
    #pragma unroll
    for (int j = 0; j < 4; j++) {
        int c0 = bn + tc + j, c1 = bn + 64 + tc + j;
        bb[j]     = (p.bias1 ? p.bias1[c0] : 0.f) + (p.bias2 ? p.bias2[c0] : 0.f);
        bb[4 + j] = (p.bias1 ? p.bias1[c1] : 0.f) + (p.bias2 ? p.bias2[c1] : 0.f);
    }
    #pragma unroll
    for (int i = 0; i < 8; i++) {
        int row = bm + ((i < 4) ? (tr + i) : (64 + tr + i - 4));
        float* Cr = p.C + (size_t)row * p.ldc;
        float4 c0 = make_float4(acc[i][0] + bb[0], acc[i][1] + bb[1],
                                acc[i][2] + bb[2], acc[i][3] + bb[3]);
        float4 c1 = make_float4(acc[i][4] + bb[4], acc[i][5] + bb[5],
                                acc[i][6] + bb[6], acc[i][7] + bb[7]);
        *(float4*)(Cr + bn + tc)      = c0;
        *(float4*)(Cr + bn + 64 + tc) = c1;
    }
}

// ======================= graph epilogue: collapsed mixprop+mlp+gelu+end_conv =======================
__global__ void graph_epi_kernel(const float* __restrict__ x, const float* __restrict__ xa,
                                 const float* __restrict__ ecw, const float* __restrict__ ecb,
                                 const float* __restrict__ pqc, float* __restrict__ oe) {
    __shared__ float s_ec[512];
    __shared__ float s_pqc[96];
    __shared__ float s_ecb[4];
    int tid = threadIdx.x;  // 256
    for (int i = tid; i < 512; i += 256) s_ec[i] = ecw[i];
    if (tid < 96) s_pqc[tid] = pqc[tid];
    if (tid < 4) s_ecb[tid] = ecb[tid];
    __syncthreads();
    int idx = blockIdx.x * 256 + tid;
    int b = idx >> 9, v = idx & 511;
    float xv[4], xav[4];
    #pragma unroll
    for (int l = 0; l < 4; l++) {
        xv[l]  = x [(size_t)(b * 4 + l) * 512 + v];
        xav[l] = xa[(size_t)(b * 4 + l) * 512 + v];
    }
    float acc[4] = {s_ecb[0], s_ecb[1], s_ecb[2], s_ecb[3]};
    for (int c = 0; c < 32; c++) {
        float P = s_pqc[c], Q = s_pqc[32 + c], Cc = s_pqc[64 + c];
        #pragma unroll
        for (int l = 0; l < 4; l++) {
            float u = P * xv[l] + Q * xav[l] + Cc;
            float g = 0.5f * u * (1.f + erff(u * 0.70710678118654752f));
            #pragma unroll
            for (int o = 0; o < 4; o++) acc[o] += s_ec[o * 128 + c * 4 + l] * g;
        }
    }
    #pragma unroll
    for (int o = 0; o < 4; o++) oe[(size_t)(b * 4 + o) * 512 + v] = acc[o];
}

// ======================= LN(x+g) over 512 + softmax -> xg, gw =======================
__global__ void lnsm_kernel(const float* __restrict__ x, const float* __restrict__ gt,
                            const float* __restrict__ gamma, const float* __restrict__ beta,
                            float* __restrict__ xg, float* __restrict__ gw) {
    __shared__ float sh[32];
    int r = blockIdx.x, tid = threadIdx.x;  // 128 threads
    size_t off = (size_t)r * 512 + tid * 4;
    float4 a = *(const float4*)(x + off);
    float4 g = *(const float4*)(gt + off);
    float4 v = make_float4(a.x + g.x, a.y + g.y, a.z + g.z, a.w + g.w);
    float mean = blkSum(v.x + v.y + v.z + v.w, sh) * (1.f / 512.f);
    float4 d = make_float4(v.x - mean, v.y - mean, v.z - mean, v.w - mean);
    float var = blkSum(d.x * d.x + d.y * d.y + d.z * d.z + d.w * d.w, sh) * (1.f / 512.f);
    float inv = rsqrtf(var + 1e-5f);
    float4 gm = *(const float4*)(gamma + tid * 4);
    float4 bt = *(const float4*)(beta + tid * 4);
    float4 o = make_float4(d.x * inv * gm.x + bt.x, d.y * inv * gm.y + bt.y,
                           d.z * inv * gm.z + bt.z, d.w * inv * gm.w + bt.w);
    *(float4*)(xg + off) = o;
    float mx = blkMax(fmaxf(fmaxf(o.x, o.y), fmaxf(o.z, o.w)), sh);
    float4 e = make_float4(expf(o.x - mx), expf(o.y - mx), expf(o.z - mx), expf(o.w - mx));
    float s = blkSum(e.x + e.y + e.z + e.w, sh);
    float rs = 1.f / s;
    *(float4*)(gw + off) = make_float4(e.x * rs, e.y * rs, e.z * rs, e.w * rs);
}

// ======================= generic LN over 1024 =======================
__global__ void ln_kernel(const float* __restrict__ in, const float* __restrict__ gamma,
                          const float* __restrict__ beta, float* __restrict__ out) {
    __shared__ float sh[32];
    int r = blockIdx.x, tid = threadIdx.x;  // 256 threads
    size_t off = (size_t)r * 1024 + tid * 4;
    float4 v = *(const float4*)(in + off);
    float mean = blkSum(v.x + v.y + v.z + v.w, sh) * (1.f / 1024.f);
    float4 d = make_float4(v.x - mean, v.y - mean, v.z - mean, v.w - mean);
    float var = blkSum(d.x * d.x + d.y * d.y + d.z * d.z + d.w * d.w, sh) * (1.f / 1024.f);
    float inv = rsqrtf(var + 1e-5f);
    float4 gm = *(const float4*)(gamma + tid * 4);
    float4 bt = *(const float4*)(beta + tid * 4);
    float4 o = make_float4(d.x * inv * gm.x + bt.x, d.y * inv * gm.y + bt.y,
                           d.z * inv * gm.z + bt.z, d.w * inv * gm.w + bt.w);
    *(float4*)(out + off) = o;
}

// ======================= LSTM gates =======================
__global__ void lstm_gate_kernel(const float* __restrict__ z, const float* __restrict__ gw,
                                 float* __restrict__ h, float* __restrict__ c,
                                 float* __restrict__ ycat, int l, int t) {
    int d = blockIdx.y;
    int idx = blockIdx.x * 256 + threadIdx.x;  // 1024*512
    int b = idx >> 9, o = idx & 511;
    const float* zr = z + (size_t)d * 1024 * 2560 + (size_t)b * 2560;
    float zi = zr[o], zf = zr[512 + o], zo = zr[1024 + o], zc = zr[1536 + o], zs = zr[2048 + o];
    int ta = d ? 3 - t : t;
    float dw = gw[(size_t)b * 2048 + ta * 512 + o];
    size_t hoff = ((size_t)(d * 4 + l) * 1024 + b) * 512 + o;
    float it = 1.f / (1.f + expf(-zi));
    float ft = 1.f / (1.f + expf(-zf));
    float ot = 1.f / (1.f + expf(-zo));
    float ch = tanhf(zc);
    float st = (1.f / (1.f + expf(-zs))) * dw;
    float cn = ft * c[hoff] + it * ch * st;
    float hn = ot * tanhf(cn);
    c[hoff] = cn;
    h[hoff] = hn;
    if (l == 3) ycat[((size_t)b * 4 + ta) * 1024 + d * 512 + o] = hn;
}

// ======================= tiny attention (N=4) for MHA (D=256,h=4) and MIL (D=128,h=8) =======================
template <int D>
__global__ void attn_kernel(const float* __restrict__ qkv, float* __restrict__ out, float scale) {
    int b = blockIdx.x, h = blockIdx.y, tid = threadIdx.x;  // D threads
    float q[4], k[4], v[4];
    #pragma unroll
    for (int n = 0; n < 4; n++) {
        const float* base = qkv + (size_t)(b * 4 + n) * 3072 + h * D + tid;
        q[n] = base[0];
        k[n] = base[1024];
        v[n] = base[2048];
    }
    float p[16];
    #pragma unroll
    for (int n = 0; n < 4; n++)
        #pragma unroll
        for (int m = 0; m < 4; m++) p[n * 4 + m] = q[n] * k[m];
    #pragma unroll
    for (int off = 16; off > 0; off >>= 1)
        #pragma unroll
        for (int j = 0; j < 16; j++) p[j] += __shfl_down_sync(0xffffffffu, p[j], off);
    __shared__ float sp[16][8];
    int warp = tid >> 5, lane = tid & 31;
    if (lane == 0)
        #pragma unroll
        for (int j = 0; j < 16; j++) sp[j][warp] = p[j];
    __syncthreads();
    __shared__ float prob[16];
    if (tid < 4) {
        int n = tid;
        float s[4];
        #pragma unroll
        for (int m = 0; m < 4; m++) {
            float t = 0.f;
            #pragma unroll
            for (int w = 0; w < (D >> 5); w++) t += sp[n * 4 + m][w];
            s[m] = t * scale;
        }
        float mx = fmaxf(fmaxf(s[0], s[1]), fmaxf(s[2], s[3]));
        float e[4], sum = 0.f;
        #pragma unroll
        for (int m = 0; m < 4; m++) { e[m] = expf(s[m] - mx); sum += e[m]; }
        float inv = 1.f / sum;
        #pragma unroll
        for (int m = 0; m < 4; m++) prob[n * 4 + m] = e[m] * inv;
    }
    __syncthreads();
    #pragma unroll
    for (int n = 0; n < 4; n++) {
        float o = 0.f;
        #pragma unroll
        for (int m = 0; m < 4; m++) o += prob[n * 4 + m] * v[m];
        out[(size_t)(b * 4 + n) * 1024 + h * D + tid] = o;
    }
}

// ======================= final: gating + pwconv + fc =======================
__global__ void final_kernel(const float* __restrict__ y1, const float* __restrict__ zln,
                             const float* __restrict__ pw_w, const float* __restrict__ pw_b,
                             const float* __restrict__ fc_w, const float* __restrict__ fc_b,
                             float* __restrict__ out_fc, float* __restrict__ out_xf) {
    __shared__ float s[4][1024];
    __shared__ float xf[1024];
    __shared__ float sh[32];
    int b = blockIdx.x, tid = threadIdx.x;  // 256
    for (int i = tid; i < 4096; i += 256) {
        int t = i >> 10, j = i & 1023;
        float yv = y1 [(size_t)(b * 4 + t) * 1024 + j];
        float zv = zln[(size_t)(b * 4 + t) * 1024 + j];
        s[t][j] = yv * (1.f / (1.f + expf(-zv)));
    }
    __syncthreads();
    float w[12];
    #pragma unroll
    for (int i = 0; i < 12; i++) w[i] = pw_w[i];
    float pb = pw_b[0];
    for (int j = tid; j < 1024; j += 256) {
        float acc = pb;
        #pragma unroll
        for (int t = 0; t < 4; t++) {
            if (j > 0)    acc += w[t * 3 + 0] * s[t][j - 1];
                          acc += w[t * 3 + 1] * s[t][j];
            if (j < 1023) acc += w[t * 3 + 2] * s[t][j + 1];
        }
        xf[j] = acc;
        out_xf[(size_t)b * 1024 + j] = acc;
    }
    __syncthreads();
    float acc7[7] = {0.f, 0.f, 0.f, 0.f, 0.f, 0.f, 0.f};
    for (int j = tid; j < 1024; j += 256) {
        float xv = xf[j];
        #pragma unroll
        for (int o = 0; o < 7; o++) acc7[o] += xv * fc_w[o * 1024 + j];
    }
    for (int o = 0; o < 7; o++) {
        float r = blkSum(acc7[o], sh);
        if (tid == 0) out_fc[b * 7 + o] = r + fc_b[o];
    }
}

// ======================= host orchestration =======================
static void gemm1(const float* A, int lda, const float* B, int ldb, const float* bias,
                  float* C, int ldc, int M, int N, int K) {
    GemmP p;
    p.A1 = A; p.A2 = A; p.B1 = B; p.B2 = B;
    p.bias1 = bias; p.bias2 = nullptr; p.C = C;
    p.lda1 = lda; p.lda2 = lda; p.ldb1 = ldb; p.ldb2 = ldb; p.ldc = ldc;
    dim3 grid(N / 128, M / 128, 1);
    sgemm_kernel<<<grid, 256>>>(p, p, M, N, K, K);
}

extern "C" void kernel_launch(void* const* d_in, const int* in_sizes, int n_in,
                              void* d_out, int out_size) {
    (void)in_sizes; (void)n_in;
    const float* x       = (const float*)d_in[0];
    const float* nv1     = (const float*)d_in[1];
    const float* nv2     = (const float*)d_in[2];
    const float* sc_w    = (const float*)d_in[3];
    const float* sc_b    = (const float*)d_in[4];
    const float* mp_w    = (const float*)d_in[5];
    const float* mp_b    = (const float*)d_in[6];
    const float* ec_w    = (const float*)d_in[7];
    const float* ec_b    = (const float*)d_in[8];
    const float* gbl_w   = (const float*)d_in[9];
    const float* gbl_b   = (const float*)d_in[10];
    const float* gbln_g  = (const float*)d_in[11];
    const float* gbln_b  = (const float*)d_in[12];
    const float* lstm_W  = (const float*)d_in[13];
    const float* lstm_Wb = (const float*)d_in[14];
    const float* lstm_U  = (const float*)d_in[15];
    const float* lstm_Ub = (const float*)d_in[16];
    const float* min_w   = (const float*)d_in[17];
    const float* min_b   = (const float*)d_in[18];
    const float* mout_w  = (const float*)d_in[19];
    const float* mout_b  = (const float*)d_in[20];
    const float* ln1_g   = (const float*)d_in[21];
    const float* ln1_b   = (const float*)d_in[22];
    const float* qkv_w   = (const float*)d_in[23];
    const float* dmin_g  = (const float*)d_in[24];
    const float* dmin_b  = (const float*)d_in[25];
    const float* pw_w    = (const float*)d_in[26];
    const float* pw_b    = (const float*)d_in[27];
    const float* fc_w    = (const float*)d_in[28];
    const float* fc_b    = (const float*)d_in[29];

    static bool init = false;
    static float *p_adj, *p_pqc, *p_xa, *p_oe, *p_gt, *p_xg, *p_gw, *p_h, *p_c, *p_z,
                 *p_ycat, *p_qkv, *p_att, *p_proj, *p_y1, *p_milz, *p_zln, *p_dfc, *p_dxf;
    if (!init) {
        void* t;
        cudaGetSymbolAddress(&t, g_adj);  p_adj  = (float*)t;
        cudaGetSymbolAddress(&t, g_pqc);  p_pqc  = (float*)t;
        cudaGetSymbolAddress(&t, g_xa);   p_xa   = (float*)t;
        cudaGetSymbolAddress(&t, g_oe);   p_oe   = (float*)t;
        cudaGetSymbolAddress(&t, g_gt);   p_gt   = (float*)t;
        cudaGetSymbolAddress(&t, g_xg);   p_xg   = (float*)t;
        cudaGetSymbolAddress(&t, g_gw);   p_gw   = (float*)t;
        cudaGetSymbolAddress(&t, g_h);    p_h    = (float*)t;
        cudaGetSymbolAddress(&t, g_c);    p_c    = (float*)t;
        cudaGetSymbolAddress(&t, g_z);    p_z    = (float*)t;
        cudaGetSymbolAddress(&t, g_ycat); p_ycat = (float*)t;
        cudaGetSymbolAddress(&t, g_qkv);  p_qkv  = (float*)t;
        cudaGetSymbolAddress(&t, g_att);  p_att  = (float*)t;
        cudaGetSymbolAddress(&t, g_proj); p_proj = (float*)t;
        cudaGetSymbolAddress(&t, g_y1);   p_y1   = (float*)t;
        cudaGetSymbolAddress(&t, g_milz); p_milz = (float*)t;
        cudaGetSymbolAddress(&t, g_zln);  p_zln  = (float*)t;
        cudaGetSymbolAddress(&t, g_dfc);  p_dfc  = (float*)t;
        cudaGetSymbolAddress(&t, g_dxf);  p_dxf  = (float*)t;
        init = true;
    }

    // ---- graph block ----
    adj_kernel<<<512, 128>>>(nv1, nv2, p_adj);
    pqc_kernel<<<1, 32>>>(mp_w, mp_b, sc_w, sc_b, p_pqc);
    gemm1(x, 512, p_adj, 512, nullptr, p_xa, 512, 4096, 512, 512);        // xa = X @ a^T
    graph_epi_kernel<<<2048, 256>>>(x, p_xa, ec_w, ec_b, p_pqc, p_oe);
    gemm1(p_oe, 512, gbl_w, 512, gbl_b, p_gt, 512, 4096, 512, 512);       // g = oe @ gbl_w^T
    lnsm_kernel<<<4096, 128>>>(x, p_gt, gbln_g, gbln_b, p_xg, p_gw);

    // ---- BiLSTM (dirs fused via blockIdx.z; fused [x;h]@[W;U]^T GEMM) ----
    cudaMemsetAsync(p_h, 0, sizeof(float) * 2 * 4 * 1024 * 512, 0);
    cudaMemsetAsync(p_c, 0, sizeof(float) * 2 * 4 * 1024 * 512, 0);
    for (int t = 0; t < 4; t++) {
        for (int l = 0; l < 4; l++) {
            GemmP pp[2];
            for (int d = 0; d < 2; d++) {
                int ta = d ? 3 - t : t;
                GemmP& p = pp[d];
                p.A1 = (l == 0) ? (p_xg + ta * 512)
                                : (p_h + (size_t)(d * 4 + (l - 1)) * 1024 * 512);
                p.lda1 = (l == 0) ? 2048 : 512;
                p.A2 = p_h + (size_t)(d * 4 + l) * 1024 * 512;
                p.lda2 = 512;
                p.B1 = lstm_W + (size_t)(d * 4 + l) * 5 * 512 * 512;
                p.ldb1 = 512;
                p.B2 = lstm_U + (size_t)(d * 4 + l) * 5 * 512 * 512;
                p.ldb2 = 512;
                p.bias1 = lstm_Wb + (size_t)(d * 4 + l) * 2560;
                p.bias2 = lstm_Ub + (size_t)(d * 4 + l) * 2560;
                p.C = p_z + (size_t)d * 1024 * 2560;
                p.ldc = 2560;
            }
            sgemm_kernel<<<dim3(20, 8, 2), 256>>>(pp[0], pp[1], 1024, 2560, 1024, 512);
            lstm_gate_kernel<<<dim3(2048, 2), 256>>>(p_z, p_gw, p_h, p_c, p_ycat, l, t);
        }
    }

    // ---- MHA ----
    gemm1(p_ycat, 1024, min_w, 1024, min_b, p_qkv, 3072, 4096, 3072, 1024);
    attn_kernel<256><<<dim3(1024, 4), 256>>>(p_qkv, p_att, 1.f / 16.f);
    gemm1(p_att, 1024, mout_w, 1024, mout_b, p_proj, 1024, 4096, 1024, 1024);
    ln_kernel<<<4096, 256>>>(p_proj, ln1_g, ln1_b, p_y1);

    // ---- MIL attention ----
    gemm1(p_y1, 1024, qkv_w, 1024, nullptr, p_qkv, 3072, 4096, 3072, 1024);
    attn_kernel<128><<<dim3(1024, 8), 128>>>(p_qkv, p_milz, 0.08838834764831845f);
    ln_kernel<<<4096, 256>>>(p_milz, dmin_g, dmin_b, p_zln);

    // ---- gating + pwconv + fc ----
    float* out = (float*)d_out;
    float *ofc, *oxf;
    if (out_size >= 7168 + 1048576) { ofc = out; oxf = out + 7168; }
    else if (out_size == 7168)      { ofc = out; oxf = p_dxf; }
    else                            { oxf = out; ofc = p_dfc; }
    final_kernel<<<1024, 256>>>(p_y1, p_zln, pw_w, pw_b, fc_w, fc_b, ofc, oxf);
}

// round 3
// speedup vs baseline: 2.3448x; 2.3448x over previous
#include <cuda_runtime.h>
#include <math.h>
#include <stdint.h>

// ======================= scratch (static device memory) =======================
__device__ float g_adj [512*512];
__device__ float g_pqc [96];
__device__ float g_xa  [4096*512];
__device__ float g_oe  [4096*512];
__device__ float g_gt  [4096*512];
__device__ float g_xg  [4096*512];
__device__ float g_gw  [4096*512];
__device__ float g_h   [2*4*1024*512];
__device__ float g_c   [2*4*1024*512];
__device__ float g_z   [2*1024*2560];
__device__ float g_ycat[4096*1024];
__device__ float g_qkv [4096*3072];
__device__ float g_att [4096*1024];
__device__ float g_proj[4096*1024];
__device__ float g_y1  [4096*1024];
__device__ float g_milz[4096*1024];
__device__ float g_zln [4096*1024];
__device__ float g_dfc [1024*7];
__device__ float g_dxf [1024*1024];

// ======================= tf32 mma.sync GEMM: C = A1@B1^T [+ A2@B2^T] + bias =======================
// BM=128, BN=128, BK=32, 256 threads, warp tile 32x64, double-buffered smem.
struct TG {
    const float *A1, *B1, *A2, *B2, *bias1, *bias2;
    float* C;
    int lda1, ldb1, lda2, ldb2, k1, k2, ldc;
};

#define TG_SMEM 73728   // 2 stages * (128*36 A + 128*36 B) floats * 4B

__device__ __forceinline__ uint32_t f2tf(float x) {
    uint32_t r;
    asm("cvt.rna.tf32.f32 %0, %1;" : "=r"(r) : "f"(x));
    return r;
}

__device__ __forceinline__ void mma8(float* c, uint32_t a0, uint32_t a1, uint32_t a2, uint32_t a3,
                                     uint32_t b0, uint32_t b1) {
    asm volatile(
        "mma.sync.aligned.m16n8k8.row.col.f32.tf32.tf32.f32 "
        "{%0,%1,%2,%3},{%4,%5,%6,%7},{%8,%9},{%0,%1,%2,%3};"
        : "+f"(c[0]), "+f"(c[1]), "+f"(c[2]), "+f"(c[3])
        : "r"(a0), "r"(a1), "r"(a2), "r"(a3), "r"(b0), "r"(b1));
}

__global__ void __launch_bounds__(256)
tgemm_kernel(TG pa, TG pb) {
    extern __shared__ float sm[];
    TG p = blockIdx.z ? pb : pa;
    const int tid = threadIdx.x, wid = tid >> 5, lane = tid & 31;
    const int wrow = wid & 3, wcol = wid >> 2;   // 4x2 warp grid, warp tile 32x64
    const int gid = lane >> 2, tig = lane & 3;
    const int bm = blockIdx.y * 128, bn = blockIdx.x * 128;
    const int nt1 = p.k1 >> 5, nt = nt1 + (p.k2 >> 5);
    const int lr = tid >> 1, lc = (tid & 1) * 16;

    float acc[16][4];
    #pragma unroll
    for (int i = 0; i < 16; i++)
        #pragma unroll
        for (int j = 0; j < 4; j++) acc[i][j] = 0.f;

    float4 ra[4], rb[4];

    auto ldg = [&](int it) {
        const float *Ap, *Bp;
        int lda, ldb, k0;
        if (it < nt1) { Ap = p.A1; lda = p.lda1; Bp = p.B1; ldb = p.ldb1; k0 = it * 32; }
        else          { Ap = p.A2; lda = p.lda2; Bp = p.B2; ldb = p.ldb2; k0 = (it - nt1) * 32; }
        const float* ar = Ap + (size_t)(bm + lr) * lda + k0 + lc;
        const float* br = Bp + (size_t)(bn + lr) * ldb + k0 + lc;
        #pragma unroll
        for (int i = 0; i < 4; i++) ra[i] = *(const float4*)(ar + 4 * i);
        #pragma unroll
        for (int i = 0; i < 4; i++) rb[i] = *(const float4*)(br + 4 * i);
    };

    auto sts = [&](int s) {
        uint32_t* A = (uint32_t*)sm + s * 9216 + lr * 36 + lc;
        uint32_t* B = A + 4608;
        #pragma unroll
        for (int i = 0; i < 4; i++) {
            uint4 v = make_uint4(f2tf(ra[i].x), f2tf(ra[i].y), f2tf(ra[i].z), f2tf(ra[i].w));
            *(uint4*)(A + 4 * i) = v;
        }
        #pragma unroll
        for (int i = 0; i < 4; i++) {
            uint4 v = make_uint4(f2tf(rb[i].x), f2tf(rb[i].y), f2tf(rb[i].z), f2tf(rb[i].w));
            *(uint4*)(B + 4 * i) = v;
        }
    };

    auto compute = [&](int s) {
        const uint32_t* A = (const uint32_t*)sm + s * 9216;
        const uint32_t* B = A + 4608;
        #pragma unroll
        for (int ks = 0; ks < 4; ks++) {
            int k = ks * 8 + tig;
            uint32_t af[2][4];
            #pragma unroll
            for (int mi = 0; mi < 2; mi++) {
                int r = wrow * 32 + mi * 16 + gid;
                af[mi][0] = A[r * 36 + k];
                af[mi][1] = A[(r + 8) * 36 + k];
                af[mi][2] = A[r * 36 + k + 4];
                af[mi][3] = A[(r + 8) * 36 + k + 4];
            }
            #pragma unroll
            for (int nj = 0; nj < 8; nj++) {
                int n = wcol * 64 + nj * 8 + gid;
                uint32_t b0 = B[n * 36 + k], b1 = B[n * 36 + k + 4];
                mma8(acc[nj],     af[0][0], af[0][1], af[0][2], af[0][3], b0, b1);
                mma8(acc[8 + nj], af[1][0], af[1][1], af[1][2], af[1][3], b0, b1);
            }
        }
    };

    ldg(0);
    sts(0);
    __syncthreads();
    for (int it = 0; it < nt; it++) {
        if (it + 1 < nt) ldg(it + 1);
        compute(it & 1);
        if (it + 1 < nt) sts((it + 1) & 1);
        __syncthreads();
    }

    // epilogue
    float2 bv[8];
    #pragma unroll
    for (int nj = 0; nj < 8; nj++) {
        int c = bn + wcol * 64 + nj * 8 + 2 * tig;
        float2 b = make_float2(0.f, 0.f);
        if (p.bias1) { float2 t = *(const float2*)(p.bias1 + c); b.x += t.x; b.y += t.y; }
        if (p.bias2) { float2 t = *(const float2*)(p.bias2 + c); b.x += t.x; b.y += t.y; }
        bv[nj] = b;
    }
    #pragma unroll
    for (int mi = 0; mi < 2; mi++) {
        int r0 = bm + wrow * 32 + mi * 16 + gid;
        #pragma unroll
        for (int nj = 0; nj < 8; nj++) {
            int c = bn + wcol * 64 + nj * 8 + 2 * tig;
            float* C0 = p.C + (size_t)r0 * p.ldc + c;
            float* C1 = p.C + (size_t)(r0 + 8) * p.ldc + c;
            *(float2*)C0 = make_float2(acc[mi * 8 + nj][0] + bv[nj].x, acc[mi * 8 + nj][1] + bv[nj].y);
            *(float2*)C1 = make_float2(acc[mi * 8 + nj][2] + bv[nj].x, acc[mi * 8 + nj][3] + bv[nj].y);
        }
    }
}

// ======================= block reduction helpers =======================
__device__ __forceinline__ float blkSum(float v, float* sh) {
    int tid = threadIdx.x;
    #pragma unroll
    for (int o = 16; o > 0; o >>= 1) v += __shfl_down_sync(0xffffffffu, v, o);
    __syncthreads();
    if ((tid & 31) == 0) sh[tid >> 5] = v;
    __syncthreads();
    if (tid < 32) {
        float x = (tid < ((int)blockDim.x >> 5)) ? sh[tid] : 0.f;
        #pragma unroll
        for (int o = 16; o > 0; o >>= 1) x += __shfl_down_sync(0xffffffffu, x, o);
        if (tid == 0) sh[0] = x;
    }
    __syncthreads();
    return sh[0];
}

__device__ __forceinline__ float blkMax(float v, float* sh) {
    int tid = threadIdx.x;
    #pragma unroll
    for (int o = 16; o > 0; o >>= 1) v = fmaxf(v, __shfl_down_sync(0xffffffffu, v, o));
    __syncthreads();
    if ((tid & 31) == 0) sh[tid >> 5] = v;
    __syncthreads();
    if (tid < 32) {
        float x = (tid < ((int)blockDim.x >> 5)) ? sh[tid] : -3.4e38f;
        #pragma unroll
        for (int o = 16; o > 0; o >>= 1) x = fmaxf(x, __shfl_down_sync(0xffffffffu, x, o));
        if (tid == 0) sh[0] = x;
    }
    __syncthreads();
    return sh[0];
}

// ======================= adjacency =======================
__global__ void adj_kernel(const float* __restrict__ nv1, const float* __restrict__ nv2,
                           float* __restrict__ a) {
    __shared__ float n1[32];
    __shared__ float row[512];
    __shared__ float sh[32];
    int v = blockIdx.x, tid = threadIdx.x;
    if (tid < 32) n1[tid] = nv1[v * 32 + tid];
    __syncthreads();
    float mx = -3.4e38f;
    #pragma unroll
    for (int i = 0; i < 4; i++) {
        int j = i * 128 + tid;
        float r = 0.f;
        #pragma unroll
        for (int k = 0; k < 32; k++) r += n1[k] * nv2[k * 512 + j];
        r = fmaxf(r, 0.f);
        row[j] = r;
        mx = fmaxf(mx, r);
    }
    mx = blkMax(mx, sh);
    float ssum = 0.f;
    #pragma unroll
    for (int i = 0; i < 4; i++) {
        int j = i * 128 + tid;
        float e = expf(row[j] - mx);
        row[j] = e;
        ssum += e;
    }
    ssum = blkSum(ssum, sh);
    float inv = 1.f / ssum;
    #pragma unroll
    for (int i = 0; i < 4; i++) {
        int j = i * 128 + tid;
        a[v * 512 + j] = (row[j] * inv + (j == v ? 1.f : 0.f)) * 0.5f;
    }
}

// ======================= P/Q/C precompute =======================
__global__ void pqc_kernel(const float* __restrict__ mp_w, const float* __restrict__ mp_b,
                           const float* __restrict__ sc_w, const float* __restrict__ sc_b,
                           float* __restrict__ pqc) {
    int o = threadIdx.x;
    float a1 = 0.f, a2 = 0.f, cc = 0.f;
    for (int c = 0; c < 32; c++) {
        float w1 = mp_w[o * 64 + c], w2 = mp_w[o * 64 + 32 + c];
        a1 += w1 * sc_w[c];
        a2 += w2 * sc_w[c];
        cc += (w1 + w2) * sc_b[c];
    }
    cc += mp_b[o];
    pqc[o]      = a1 + 0.7f * a2;
    pqc[32 + o] = 0.3f * a2;
    pqc[64 + o] = cc;
}

// ======================= graph epilogue =======================
__global__ void graph_epi_kernel(const float* __restrict__ x, const float* __restrict__ xa,
                                 const float* __restrict__ ecw, const float* __restrict__ ecb,
                                 const float* __restrict__ pqc, float* __restrict__ oe) {
    __shared__ float s_ec[512];
    __shared__ float s_pqc[96];
    __shared__ float s_ecb[4];
    int tid = threadIdx.x;
    for (int i = tid; i < 512; i += 256) s_ec[i] = ecw[i];
    if (tid < 96) s_pqc[tid] = pqc[tid];
    if (tid < 4) s_ecb[tid] = ecb[tid];
    __syncthreads();
    int idx = blockIdx.x * 256 + tid;
    int b = idx >> 9, v = idx & 511;
    float xv[4], xav[4];
    #pragma unroll
    for (int l = 0; l < 4; l++) {
        xv[l]  = x [(size_t)(b * 4 + l) * 512 + v];
        xav[l] = xa[(size_t)(b * 4 + l) * 512 + v];
    }
    float acc[4] = {s_ecb[0], s_ecb[1], s_ecb[2], s_ecb[3]};
    for (int c = 0; c < 32; c++) {
        float P = s_pqc[c], Q = s_pqc[32 + c], Cc = s_pqc[64 + c];
        #pragma unroll
        for (int l = 0; l < 4; l++) {
            float u = P * xv[l] + Q * xav[l] + Cc;
            float g = 0.5f * u * (1.f + erff(u * 0.70710678118654752f));
            #pragma unroll
            for (int o = 0; o < 4; o++) acc[o] += s_ec[o * 128 + c * 4 + l] * g;
        }
    }
    #pragma unroll
    for (int o = 0; o < 4; o++) oe[(size_t)(b * 4 + o) * 512 + v] = acc[o];
}

// ======================= LN(x+g) + softmax =======================
__global__ void lnsm_kernel(const float* __restrict__ x, const float* __restrict__ gt,
                            const float* __restrict__ gamma, const float* __restrict__ beta,
                            float* __restrict__ xg, float* __restrict__ gw) {
    __shared__ float sh[32];
    int r = blockIdx.x, tid = threadIdx.x;
    size_t off = (size_t)r * 512 + tid * 4;
    float4 a = *(const float4*)(x + off);
    float4 g = *(const float4*)(gt + off);
    float4 v = make_float4(a.x + g.x, a.y + g.y, a.z + g.z, a.w + g.w);
    float mean = blkSum(v.x + v.y + v.z + v.w, sh) * (1.f / 512.f);
    float4 d = make_float4(v.x - mean, v.y - mean, v.z - mean, v.w - mean);
    float var = blkSum(d.x * d.x + d.y * d.y + d.z * d.z + d.w * d.w, sh) * (1.f / 512.f);
    float inv = rsqrtf(var + 1e-5f);
    float4 gm = *(const float4*)(gamma + tid * 4);
    float4 bt = *(const float4*)(beta + tid * 4);
    float4 o = make_float4(d.x * inv * gm.x + bt.x, d.y * inv * gm.y + bt.y,
                           d.z * inv * gm.z + bt.z, d.w * inv * gm.w + bt.w);
    *(float4*)(xg + off) = o;
    float mx = blkMax(fmaxf(fmaxf(o.x, o.y), fmaxf(o.z, o.w)), sh);
    float4 e = make_float4(expf(o.x - mx), expf(o.y - mx), expf(o.z - mx), expf(o.w - mx));
    float s = blkSum(e.x + e.y + e.z + e.w, sh);
    float rs = 1.f / s;
    *(float4*)(gw + off) = make_float4(e.x * rs, e.y * rs, e.z * rs, e.w * rs);
}

// ======================= LN over 1024 =======================
__global__ void ln_kernel(const float* __restrict__ in, const float* __restrict__ gamma,
                          const float* __restrict__ beta, float* __restrict__ out) {
    __shared__ float sh[32];
    int r = blockIdx.x, tid = threadIdx.x;
    size_t off = (size_t)r * 1024 + tid * 4;
    float4 v = *(const float4*)(in + off);
    float mean = blkSum(v.x + v.y + v.z + v.w, sh) * (1.f / 1024.f);
    float4 d = make_float4(v.x - mean, v.y - mean, v.z - mean, v.w - mean);
    float var = blkSum(d.x * d.x + d.y * d.y + d.z * d.z + d.w * d.w, sh) * (1.f / 1024.f);
    float inv = rsqrtf(var + 1e-5f);
    float4 gm = *(const float4*)(gamma + tid * 4);
    float4 bt = *(const float4*)(beta + tid * 4);
    float4 o = make_float4(d.x * inv * gm.x + bt.x, d.y * inv * gm.y + bt.y,
                           d.z * inv * gm.z + bt.z, d.w * inv * gm.w + bt.w);
    *(float4*)(out + off) = o;
}

// ======================= LSTM gates =======================
__global__ void lstm_gate_kernel(const float* __restrict__ z, const float* __restrict__ gw,
                                 float* __restrict__ h, float* __restrict__ c,
                                 float* __restrict__ ycat, int l, int t) {
    int d = blockIdx.y;
    int idx = blockIdx.x * 256 + threadIdx.x;
    int b = idx >> 9, o = idx & 511;
    const float* zr = z + (size_t)d * 1024 * 2560 + (size_t)b * 2560;
    float zi = zr[o], zf = zr[512 + o], zo = zr[1024 + o], zc = zr[1536 + o], zs = zr[2048 + o];
    int ta = d ? 3 - t : t;
    float dw = gw[(size_t)b * 2048 + ta * 512 + o];
    size_t hoff = ((size_t)(d * 4 + l) * 1024 + b) * 512 + o;
    float it = 1.f / (1.f + expf(-zi));
    float ft = 1.f / (1.f + expf(-zf));
    float ot = 1.f / (1.f + expf(-zo));
    float ch = tanhf(zc);
    float st = (1.f / (1.f + expf(-zs))) * dw;
    float cn = ft * c[hoff] + it * ch * st;
    float hn = ot * tanhf(cn);
    c[hoff] = cn;
    h[hoff] = hn;
    if (l == 3) ycat[((size_t)b * 4 + ta) * 1024 + d * 512 + o] = hn;
}

// ======================= tiny attention (N=4) =======================
template <int D>
__global__ void attn_kernel(const float* __restrict__ qkv, float* __restrict__ out, float scale) {
    int b = blockIdx.x, h = blockIdx.y, tid = threadIdx.x;
    float q[4], k[4], v[4];
    #pragma unroll
    for (int n = 0; n < 4; n++) {
        const float* base = qkv + (size_t)(b * 4 + n) * 3072 + h * D + tid;
        q[n] = base[0];
        k[n] = base[1024];
        v[n] = base[2048];
    }
    float p[16];
    #pragma unroll
    for (int n = 0; n < 4; n++)
        #pragma unroll
        for (int m = 0; m < 4; m++) p[n * 4 + m] = q[n] * k[m];
    #pragma unroll
    for (int off = 16; off > 0; off >>= 1)
        #pragma unroll
        for (int j = 0; j < 16; j++) p[j] += __shfl_down_sync(0xffffffffu, p[j], off);
    __shared__ float sp[16][8];
    int warp = tid >> 5, lane = tid & 31;
    if (lane == 0)
        #pragma unroll
        for (int j = 0; j < 16; j++) sp[j][warp] = p[j];
    __syncthreads();
    __shared__ float prob[16];
    if (tid < 4) {
        int n = tid;
        float s[4];
        #pragma unroll
        for (int m = 0; m < 4; m++) {
            float t = 0.f;
            #pragma unroll
            for (int w = 0; w < (D >> 5); w++) t += sp[n * 4 + m][w];
            s[m] = t * scale;
        }
        float mx = fmaxf(fmaxf(s[0], s[1]), fmaxf(s[2], s[3]));
        float e[4], sum = 0.f;
        #pragma unroll
        for (int m = 0; m < 4; m++) { e[m] = expf(s[m] - mx); sum += e[m]; }
        float inv = 1.f / sum;
        #pragma unroll
        for (int m = 0; m < 4; m++) prob[n * 4 + m] = e[m] * inv;
    }
    __syncthreads();
    #pragma unroll
    for (int n = 0; n < 4; n++) {
        float o = 0.f;
        #pragma unroll
        for (int m = 0; m < 4; m++) o += prob[n * 4 + m] * v[m];
        out[(size_t)(b * 4 + n) * 1024 + h * D + tid] = o;
    }
}

// ======================= final: gating + pwconv + fc =======================
__global__ void final_kernel(const float* __restrict__ y1, const float* __restrict__ zln,
                             const float* __restrict__ pw_w, const float* __restrict__ pw_b,
                             const float* __restrict__ fc_w, const float* __restrict__ fc_b,
                             float* __restrict__ out_fc, float* __restrict__ out_xf) {
    __shared__ float s[4][1024];
    __shared__ float xf[1024];
    __shared__ float sh[32];
    int b = blockIdx.x, tid = threadIdx.x;
    for (int i = tid; i < 4096; i += 256) {
        int t = i >> 10, j = i & 1023;
        float yv = y1 [(size_t)(b * 4 + t) * 1024 + j];
        float zv = zln[(size_t)(b * 4 + t) * 1024 + j];
        s[t][j] = yv * (1.f / (1.f + expf(-zv)));
    }
    __syncthreads();
    float w[12];
    #pragma unroll
    for (int i = 0; i < 12; i++) w[i] = pw_w[i];
    float pb = pw_b[0];
    for (int j = tid; j < 1024; j += 256) {
        float acc = pb;
        #pragma unroll
        for (int t = 0; t < 4; t++) {
            if (j > 0)    acc += w[t * 3 + 0] * s[t][j - 1];
                          acc += w[t * 3 + 1] * s[t][j];
            if (j < 1023) acc += w[t * 3 + 2] * s[t][j + 1];
        }
        xf[j] = acc;
        out_xf[(size_t)b * 1024 + j] = acc;
    }
    __syncthreads();
    float acc7[7] = {0.f, 0.f, 0.f, 0.f, 0.f, 0.f, 0.f};
    for (int j = tid; j < 1024; j += 256) {
        float xv = xf[j];
        #pragma unroll
        for (int o = 0; o < 7; o++) acc7[o] += xv * fc_w[o * 1024 + j];
    }
    for (int o = 0; o < 7; o++) {
        float r = blkSum(acc7[o], sh);
        if (tid == 0) out_fc[b * 7 + o] = r + fc_b[o];
    }
}

// ======================= host orchestration =======================
static void tgemm(const float* A, int lda, const float* B, int ldb, const float* bias,
                  float* C, int ldc, int M, int N, int K) {
    TG p;
    p.A1 = A; p.lda1 = lda; p.B1 = B; p.ldb1 = ldb; p.k1 = K;
    p.A2 = nullptr; p.lda2 = 0; p.B2 = nullptr; p.ldb2 = 0; p.k2 = 0;
    p.bias1 = bias; p.bias2 = nullptr;
    p.C = C; p.ldc = ldc;
    dim3 grid(N / 128, M / 128, 1);
    tgemm_kernel<<<grid, 256, TG_SMEM>>>(p, p);
}

extern "C" void kernel_launch(void* const* d_in, const int* in_sizes, int n_in,
                              void* d_out, int out_size) {
    (void)in_sizes; (void)n_in;
    const float* x       = (const float*)d_in[0];
    const float* nv1     = (const float*)d_in[1];
    const float* nv2     = (const float*)d_in[2];
    const float* sc_w    = (const float*)d_in[3];
    const float* sc_b    = (const float*)d_in[4];
    const float* mp_w    = (const float*)d_in[5];
    const float* mp_b    = (const float*)d_in[6];
    const float* ec_w    = (const float*)d_in[7];
    const float* ec_b    = (const float*)d_in[8];
    const float* gbl_w   = (const float*)d_in[9];
    const float* gbl_b   = (const float*)d_in[10];
    const float* gbln_g  = (const float*)d_in[11];
    const float* gbln_b  = (const float*)d_in[12];
    const float* lstm_W  = (const float*)d_in[13];
    const float* lstm_Wb = (const float*)d_in[14];
    const float* lstm_U  = (const float*)d_in[15];
    const float* lstm_Ub = (const float*)d_in[16];
    const float* min_w   = (const float*)d_in[17];
    const float* min_b   = (const float*)d_in[18];
    const float* mout_w  = (const float*)d_in[19];
    const float* mout_b  = (const float*)d_in[20];
    const float* ln1_g   = (const float*)d_in[21];
    const float* ln1_b   = (const float*)d_in[22];
    const float* qkv_w   = (const float*)d_in[23];
    const float* dmin_g  = (const float*)d_in[24];
    const float* dmin_b  = (const float*)d_in[25];
    const float* pw_w    = (const float*)d_in[26];
    const float* pw_b    = (const float*)d_in[27];
    const float* fc_w    = (const float*)d_in[28];
    const float* fc_b    = (const float*)d_in[29];

    static bool init = false;
    static float *p_adj, *p_pqc, *p_xa, *p_oe, *p_gt, *p_xg, *p_gw, *p_h, *p_c, *p_z,
                 *p_ycat, *p_qkv, *p_att, *p_proj, *p_y1, *p_milz, *p_zln, *p_dfc, *p_dxf;
    if (!init) {
        void* t;
        cudaGetSymbolAddress(&t, g_adj);  p_adj  = (float*)t;
        cudaGetSymbolAddress(&t, g_pqc);  p_pqc  = (float*)t;
        cudaGetSymbolAddress(&t, g_xa);   p_xa   = (float*)t;
        cudaGetSymbolAddress(&t, g_oe);   p_oe   = (float*)t;
        cudaGetSymbolAddress(&t, g_gt);   p_gt   = (float*)t;
        cudaGetSymbolAddress(&t, g_xg);   p_xg   = (float*)t;
        cudaGetSymbolAddress(&t, g_gw);   p_gw   = (float*)t;
        cudaGetSymbolAddress(&t, g_h);    p_h    = (float*)t;
        cudaGetSymbolAddress(&t, g_c);    p_c    = (float*)t;
        cudaGetSymbolAddress(&t, g_z);    p_z    = (float*)t;
        cudaGetSymbolAddress(&t, g_ycat); p_ycat = (float*)t;
        cudaGetSymbolAddress(&t, g_qkv);  p_qkv  = (float*)t;
        cudaGetSymbolAddress(&t, g_att);  p_att  = (float*)t;
        cudaGetSymbolAddress(&t, g_proj); p_proj = (float*)t;
        cudaGetSymbolAddress(&t, g_y1);   p_y1   = (float*)t;
        cudaGetSymbolAddress(&t, g_milz); p_milz = (float*)t;
        cudaGetSymbolAddress(&t, g_zln);  p_zln  = (float*)t;
        cudaGetSymbolAddress(&t, g_dfc);  p_dfc  = (float*)t;
        cudaGetSymbolAddress(&t, g_dxf);  p_dxf  = (float*)t;
        cudaFuncSetAttribute(tgemm_kernel, cudaFuncAttributeMaxDynamicSharedMemorySize, TG_SMEM);
        init = true;
    }

    // ---- graph block ----
    adj_kernel<<<512, 128>>>(nv1, nv2, p_adj);
    pqc_kernel<<<1, 32>>>(mp_w, mp_b, sc_w, sc_b, p_pqc);
    tgemm(x, 512, p_adj, 512, nullptr, p_xa, 512, 4096, 512, 512);        // xa = X @ a^T
    graph_epi_kernel<<<2048, 256>>>(x, p_xa, ec_w, ec_b, p_pqc, p_oe);
    tgemm(p_oe, 512, gbl_w, 512, gbl_b, p_gt, 512, 4096, 512, 512);       // g = oe @ gbl_w^T
    lnsm_kernel<<<4096, 128>>>(x, p_gt, gbln_g, gbln_b, p_xg, p_gw);

    // ---- BiLSTM (dirs fused via blockIdx.z; fused [x;h]@[W;U]^T + both biases) ----
    cudaMemsetAsync(p_h, 0, sizeof(float) * 2 * 4 * 1024 * 512, 0);
    cudaMemsetAsync(p_c, 0, sizeof(float) * 2 * 4 * 1024 * 512, 0);
    for (int t = 0; t < 4; t++) {
        for (int l = 0; l < 4; l++) {
            TG pp[2];
            for (int d = 0; d < 2; d++) {
                int ta = d ? 3 - t : t;
                TG& p = pp[d];
                p.A1 = (l == 0) ? (p_xg + ta * 512)
                                : (p_h + (size_t)(d * 4 + (l - 1)) * 1024 * 512);
                p.lda1 = (l == 0) ? 2048 : 512;
                p.B1 = lstm_W + (size_t)(d * 4 + l) * 5 * 512 * 512;
                p.ldb1 = 512;
                p.k1 = 512;
                p.A2 = p_h + (size_t)(d * 4 + l) * 1024 * 512;
                p.lda2 = 512;
                p.B2 = lstm_U + (size_t)(d * 4 + l) * 5 * 512 * 512;
                p.ldb2 = 512;
                p.k2 = 512;
                p.bias1 = lstm_Wb + (size_t)(d * 4 + l) * 2560;
                p.bias2 = lstm_Ub + (size_t)(d * 4 + l) * 2560;
                p.C = p_z + (size_t)d * 1024 * 2560;
                p.ldc = 2560;
            }
            tgemm_kernel<<<dim3(20, 8, 2), 256, TG_SMEM>>>(pp[0], pp[1]);
            lstm_gate_kernel<<<dim3(2048, 2), 256>>>(p_z, p_gw, p_h, p_c, p_ycat, l, t);
        }
    }

    // ---- MHA ----
    tgemm(p_ycat, 1024, min_w, 1024, min_b, p_qkv, 3072, 4096, 3072, 1024);
    attn_kernel<256><<<dim3(1024, 4), 256>>>(p_qkv, p_att, 1.f / 16.f);
    tgemm(p_att, 1024, mout_w, 1024, mout_b, p_proj, 1024, 4096, 1024, 1024);
    ln_kernel<<<4096, 256>>>(p_proj, ln1_g, ln1_b, p_y1);

    // ---- MIL attention ----
    tgemm(p_y1, 1024, qkv_w, 1024, nullptr, p_qkv, 3072, 4096, 3072, 1024);
    attn_kernel<128><<<dim3(1024, 8), 128>>>(p_qkv, p_milz, 0.08838834764831845f);
    ln_kernel<<<4096, 256>>>(p_milz, dmin_g, dmin_b, p_zln);

    // ---- gating + pwconv + fc ----
    float* out = (float*)d_out;
    float *ofc, *oxf;
    if (out_size >= 7168 + 1048576) { ofc = out; oxf = out + 7168; }
    else if (out_size == 7168)      { ofc = out; oxf = p_dxf; }
    else                            { oxf = out; ofc = p_dfc; }
    final_kernel<<<1024, 256>>>(p_y1, p_zln, pw_w, pw_b, fc_w, fc_b, ofc, oxf);
}

// round 4
// speedup vs baseline: 2.5901x; 1.1046x over previous
#include <cuda_runtime.h>
#include <math.h>
#include <stdint.h>

// ======================= scratch (static device memory) =======================
__device__ float g_adj [512*512];
__device__ float g_pqc [96];
__device__ float g_xa  [4096*512];
__device__ float g_oe  [4096*512];
__device__ float g_gt  [4096*512];
__device__ float g_xg  [4096*512];
__device__ float g_gw  [4096*512];
__device__ float g_h   [2*4*1024*512];
__device__ float g_c   [2*4*1024*512];
__device__ float g_z   [8*1024*2560];
__device__ float g_ycat[4096*1024];
__device__ float g_qkv [4096*3072];
__device__ float g_att [4096*1024];
__device__ float g_proj[4096*1024];
__device__ float g_y1  [4096*1024];
__device__ float g_milz[4096*1024];
__device__ float g_zln [4096*1024];
__device__ float g_dfc [1024*7];
__device__ float g_dxf [1024*1024];

// ======================= tf32 mma.sync GEMM: C = A1@B1^T [+ A2@B2^T] + bias =======================
// BM=128, BN=128, BK=32, 256 threads, warp tile 32x64, double-buffered smem.
// Batched: up to 8 independent GEMMs per launch via blockIdx.z.
struct TG {
    const float *A1, *B1, *A2, *B2, *bias1, *bias2;
    float* C;
    int lda1, ldb1, lda2, ldb2, k1, k2, ldc;
};
struct TGBatch { TG g[8]; };

#define TG_SMEM 73728   // 2 stages * (128*36 A + 128*36 B) floats * 4B

__device__ __forceinline__ uint32_t f2tf(float x) {
    uint32_t r;
    asm("cvt.rna.tf32.f32 %0, %1;" : "=r"(r) : "f"(x));
    return r;
}

__device__ __forceinline__ void mma8(float* c, uint32_t a0, uint32_t a1, uint32_t a2, uint32_t a3,
                                     uint32_t b0, uint32_t b1) {
    asm volatile(
        "mma.sync.aligned.m16n8k8.row.col.f32.tf32.tf32.f32 "
        "{%0,%1,%2,%3},{%4,%5,%6,%7},{%8,%9},{%0,%1,%2,%3};"
        : "+f"(c[0]), "+f"(c[1]), "+f"(c[2]), "+f"(c[3])
        : "r"(a0), "r"(a1), "r"(a2), "r"(a3), "r"(b0), "r"(b1));
}

__global__ void __launch_bounds__(256, 2)
tgemm_kernel(TGBatch bat) {
    extern __shared__ float sm[];
    TG p = bat.g[blockIdx.z];
    const int tid = threadIdx.x, wid = tid >> 5, lane = tid & 31;
    const int wrow = wid & 3, wcol = wid >> 2;   // 4x2 warp grid, warp tile 32x64
    const int gid = lane >> 2, tig = lane & 3;
    const int bm = blockIdx.y * 128, bn = blockIdx.x * 128;
    const int nt1 = p.k1 >> 5, nt = nt1 + (p.k2 >> 5);
    const int lr = tid >> 1, lc = (tid & 1) * 16;

    float acc[16][4];
    #pragma unroll
    for (int i = 0; i < 16; i++)
        #pragma unroll
        for (int j = 0; j < 4; j++) acc[i][j] = 0.f;

    float4 ra[4], rb[4];

    auto ldg = [&](int it) {
        const float *Ap, *Bp;
        int lda, ldb, k0;
        if (it < nt1) { Ap = p.A1; lda = p.lda1; Bp = p.B1; ldb = p.ldb1; k0 = it * 32; }
        else          { Ap = p.A2; lda = p.lda2; Bp = p.B2; ldb = p.ldb2; k0 = (it - nt1) * 32; }
        const float* ar = Ap + (size_t)(bm + lr) * lda + k0 + lc;
        const float* br = Bp + (size_t)(bn + lr) * ldb + k0 + lc;
        #pragma unroll
        for (int i = 0; i < 4; i++) ra[i] = *(const float4*)(ar + 4 * i);
        #pragma unroll
        for (int i = 0; i < 4; i++) rb[i] = *(const float4*)(br + 4 * i);
    };

    auto sts = [&](int s) {
        uint32_t* A = (uint32_t*)sm + s * 9216 + lr * 36 + lc;
        uint32_t* B = A + 4608;
        #pragma unroll
        for (int i = 0; i < 4; i++) {
            uint4 v = make_uint4(f2tf(ra[i].x), f2tf(ra[i].y), f2tf(ra[i].z), f2tf(ra[i].w));
            *(uint4*)(A + 4 * i) = v;
        }
        #pragma unroll
        for (int i = 0; i < 4; i++) {
            uint4 v = make_uint4(f2tf(rb[i].x), f2tf(rb[i].y), f2tf(rb[i].z), f2tf(rb[i].w));
            *(uint4*)(B + 4 * i) = v;
        }
    };

    auto compute = [&](int s) {
        const uint32_t* A = (const uint32_t*)sm + s * 9216;
        const uint32_t* B = A + 4608;
        #pragma unroll
        for (int ks = 0; ks < 4; ks++) {
            int k = ks * 8 + tig;
            uint32_t af[2][4];
            #pragma unroll
            for (int mi = 0; mi < 2; mi++) {
                int r = wrow * 32 + mi * 16 + gid;
                af[mi][0] = A[r * 36 + k];
                af[mi][1] = A[(r + 8) * 36 + k];
                af[mi][2] = A[r * 36 + k + 4];
                af[mi][3] = A[(r + 8) * 36 + k + 4];
            }
            #pragma unroll
            for (int nj = 0; nj < 8; nj++) {
                int n = wcol * 64 + nj * 8 + gid;
                uint32_t b0 = B[n * 36 + k], b1 = B[n * 36 + k + 4];
                mma8(acc[nj],     af[0][0], af[0][1], af[0][2], af[0][3], b0, b1);
                mma8(acc[8 + nj], af[1][0], af[1][1], af[1][2], af[1][3], b0, b1);
            }
        }
    };

    ldg(0);
    sts(0);
    __syncthreads();
    for (int it = 0; it < nt; it++) {
        if (it + 1 < nt) ldg(it + 1);
        compute(it & 1);
        if (it + 1 < nt) sts((it + 1) & 1);
        __syncthreads();
    }

    // epilogue
    float2 bv[8];
    #pragma unroll
    for (int nj = 0; nj < 8; nj++) {
        int c = bn + wcol * 64 + nj * 8 + 2 * tig;
        float2 b = make_float2(0.f, 0.f);
        if (p.bias1) { float2 t = *(const float2*)(p.bias1 + c); b.x += t.x; b.y += t.y; }
        if (p.bias2) { float2 t = *(const float2*)(p.bias2 + c); b.x += t.x; b.y += t.y; }
        bv[nj] = b;
    }
    #pragma unroll
    for (int mi = 0; mi < 2; mi++) {
        int r0 = bm + wrow * 32 + mi * 16 + gid;
        #pragma unroll
        for (int nj = 0; nj < 8; nj++) {
            int c = bn + wcol * 64 + nj * 8 + 2 * tig;
            float* C0 = p.C + (size_t)r0 * p.ldc + c;
            float* C1 = p.C + (size_t)(r0 + 8) * p.ldc + c;
            *(float2*)C0 = make_float2(acc[mi * 8 + nj][0] + bv[nj].x, acc[mi * 8 + nj][1] + bv[nj].y);
            *(float2*)C1 = make_float2(acc[mi * 8 + nj][2] + bv[nj].x, acc[mi * 8 + nj][3] + bv[nj].y);
        }
    }
}

// ======================= block reduction helpers =======================
__device__ __forceinline__ float blkSum(float v, float* sh) {
    int tid = threadIdx.x;
    #pragma unroll
    for (int o = 16; o > 0; o >>= 1) v += __shfl_down_sync(0xffffffffu, v, o);
    __syncthreads();
    if ((tid & 31) == 0) sh[tid >> 5] = v;
    __syncthreads();
    if (tid < 32) {
        float x = (tid < ((int)blockDim.x >> 5)) ? sh[tid] : 0.f;
        #pragma unroll
        for (int o = 16; o > 0; o >>= 1) x += __shfl_down_sync(0xffffffffu, x, o);
        if (tid == 0) sh[0] = x;
    }
    __syncthreads();
    return sh[0];
}

__device__ __forceinline__ float blkMax(float v, float* sh) {
    int tid = threadIdx.x;
    #pragma unroll
    for (int o = 16; o > 0; o >>= 1) v = fmaxf(v, __shfl_down_sync(0xffffffffu, v, o));
    __syncthreads();
    if ((tid & 31) == 0) sh[tid >> 5] = v;
    __syncthreads();
    if (tid < 32) {
        float x = (tid < ((int)blockDim.x >> 5)) ? sh[tid] : -3.4e38f;
        #pragma unroll
        for (int o = 16; o > 0; o >>= 1) x = fmaxf(x, __shfl_down_sync(0xffffffffu, x, o));
        if (tid == 0) sh[0] = x;
    }
    __syncthreads();
    return sh[0];
}

// ======================= adjacency =======================
__global__ void adj_kernel(const float* __restrict__ nv1, const float* __restrict__ nv2,
                           float* __restrict__ a) {
    __shared__ float n1[32];
    __shared__ float row[512];
    __shared__ float sh[32];
    int v = blockIdx.x, tid = threadIdx.x;
    if (tid < 32) n1[tid] = nv1[v * 32 + tid];
    __syncthreads();
    float mx = -3.4e38f;
    #pragma unroll
    for (int i = 0; i < 4; i++) {
        int j = i * 128 + tid;
        float r = 0.f;
        #pragma unroll
        for (int k = 0; k < 32; k++) r += n1[k] * nv2[k * 512 + j];
        r = fmaxf(r, 0.f);
        row[j] = r;
        mx = fmaxf(mx, r);
    }
    mx = blkMax(mx, sh);
    float ssum = 0.f;
    #pragma unroll
    for (int i = 0; i < 4; i++) {
        int j = i * 128 + tid;
        float e = expf(row[j] - mx);
        row[j] = e;
        ssum += e;
    }
    ssum = blkSum(ssum, sh);
    float inv = 1.f / ssum;
    #pragma unroll
    for (int i = 0; i < 4; i++) {
        int j = i * 128 + tid;
        a[v * 512 + j] = (row[j] * inv + (j == v ? 1.f : 0.f)) * 0.5f;
    }
}

// ======================= P/Q/C precompute =======================
__global__ void pqc_kernel(const float* __restrict__ mp_w, const float* __restrict__ mp_b,
                           const float* __restrict__ sc_w, const float* __restrict__ sc_b,
                           float* __restrict__ pqc) {
    int o = threadIdx.x;
    float a1 = 0.f, a2 = 0.f, cc = 0.f;
    for (int c = 0; c < 32; c++) {
        float w1 = mp_w[o * 64 + c], w2 = mp_w[o * 64 + 32 + c];
        a1 += w1 * sc_w[c];
        a2 += w2 * sc_w[c];
        cc += (w1 + w2) * sc_b[c];
    }
    cc += mp_b[o];
    pqc[o]      = a1 + 0.7f * a2;
    pqc[32 + o] = 0.3f * a2;
    pqc[64 + o] = cc;
}

// ======================= graph epilogue =======================
__global__ void graph_epi_kernel(const float* __restrict__ x, const float* __restrict__ xa,
                                 const float* __restrict__ ecw, const float* __restrict__ ecb,
                                 const float* __restrict__ pqc, float* __restrict__ oe) {
    __shared__ float s_ec[512];
    __shared__ float s_pqc[96];
    __shared__ float s_ecb[4];
    int tid = threadIdx.x;
    for (int i = tid; i < 512; i += 256) s_ec[i] = ecw[i];
    if (tid < 96) s_pqc[tid] = pqc[tid];
    if (tid < 4) s_ecb[tid] = ecb[tid];
    __syncthreads();
    int idx = blockIdx.x * 256 + tid;
    int b = idx >> 9, v = idx & 511;
    float xv[4], xav[4];
    #pragma unroll
    for (int l = 0; l < 4; l++) {
        xv[l]  = x [(size_t)(b * 4 + l) * 512 + v];
        xav[l] = xa[(size_t)(b * 4 + l) * 512 + v];
    }
    float acc[4] = {s_ecb[0], s_ecb[1], s_ecb[2], s_ecb[3]};
    for (int c = 0; c < 32; c++) {
        float P = s_pqc[c], Q = s_pqc[32 + c], Cc = s_pqc[64 + c];
        #pragma unroll
        for (int l = 0; l < 4; l++) {
            float u = P * xv[l] + Q * xav[l] + Cc;
            float g = 0.5f * u * (1.f + erff(u * 0.70710678118654752f));
            #pragma unroll
            for (int o = 0; o < 4; o++) acc[o] += s_ec[o * 128 + c * 4 + l] * g;
        }
    }
    #pragma unroll
    for (int o = 0; o < 4; o++) oe[(size_t)(b * 4 + o) * 512 + v] = acc[o];
}

// ======================= LN(x+g) + softmax =======================
__global__ void lnsm_kernel(const float* __restrict__ x, const float* __restrict__ gt,
                            const float* __restrict__ gamma, const float* __restrict__ beta,
                            float* __restrict__ xg, float* __restrict__ gw) {
    __shared__ float sh[32];
    int r = blockIdx.x, tid = threadIdx.x;
    size_t off = (size_t)r * 512 + tid * 4;
    float4 a = *(const float4*)(x + off);
    float4 g = *(const float4*)(gt + off);
    float4 v = make_float4(a.x + g.x, a.y + g.y, a.z + g.z, a.w + g.w);
    float mean = blkSum(v.x + v.y + v.z + v.w, sh) * (1.f / 512.f);
    float4 d = make_float4(v.x - mean, v.y - mean, v.z - mean, v.w - mean);
    float var = blkSum(d.x * d.x + d.y * d.y + d.z * d.z + d.w * d.w, sh) * (1.f / 512.f);
    float inv = rsqrtf(var + 1e-5f);
    float4 gm = *(const float4*)(gamma + tid * 4);
    float4 bt = *(const float4*)(beta + tid * 4);
    float4 o = make_float4(d.x * inv * gm.x + bt.x, d.y * inv * gm.y + bt.y,
                           d.z * inv * gm.z + bt.z, d.w * inv * gm.w + bt.w);
    *(float4*)(xg + off) = o;
    float mx = blkMax(fmaxf(fmaxf(o.x, o.y), fmaxf(o.z, o.w)), sh);
    float4 e = make_float4(expf(o.x - mx), expf(o.y - mx), expf(o.z - mx), expf(o.w - mx));
    float s = blkSum(e.x + e.y + e.z + e.w, sh);
    float rs = 1.f / s;
    *(float4*)(gw + off) = make_float4(e.x * rs, e.y * rs, e.z * rs, e.w * rs);
}

// ======================= LN over 1024 =======================
__global__ void ln_kernel(const float* __restrict__ in, const float* __restrict__ gamma,
                          const float* __restrict__ beta, float* __restrict__ out) {
    __shared__ float sh[32];
    int r = blockIdx.x, tid = threadIdx.x;
    size_t off = (size_t)r * 1024 + tid * 4;
    float4 v = *(const float4*)(in + off);
    float mean = blkSum(v.x + v.y + v.z + v.w, sh) * (1.f / 1024.f);
    float4 d = make_float4(v.x - mean, v.y - mean, v.z - mean, v.w - mean);
    float var = blkSum(d.x * d.x + d.y * d.y + d.z * d.z + d.w * d.w, sh) * (1.f / 1024.f);
    float inv = rsqrtf(var + 1e-5f);
    float4 gm = *(const float4*)(gamma + tid * 4);
    float4 bt = *(const float4*)(beta + tid * 4);
    float4 o = make_float4(d.x * inv * gm.x + bt.x, d.y * inv * gm.y + bt.y,
                           d.z * inv * gm.z + bt.z, d.w * inv * gm.w + bt.w);
    *(float4*)(out + off) = o;
}

// ======================= LSTM gates (wavefront-batched over cells) =======================
struct GateMeta { int dir[8], lay[8], tim[8]; };

__global__ void lstm_gate_wave(const float* __restrict__ z, const float* __restrict__ gw,
                               float* __restrict__ h, float* __restrict__ c,
                               float* __restrict__ ycat, GateMeta gm) {
    int cell = blockIdx.y;
    int dd = gm.dir[cell], l = gm.lay[cell], t = gm.tim[cell];
    int idx = blockIdx.x * 256 + threadIdx.x;
    int b = idx >> 9, o = idx & 511;
    const float* zr = z + (size_t)cell * 1024 * 2560 + (size_t)b * 2560;
    float zi = zr[o], zf = zr[512 + o], zo = zr[1024 + o], zc = zr[1536 + o], zs = zr[2048 + o];
    int ta = dd ? 3 - t : t;
    float dw = gw[(size_t)b * 2048 + ta * 512 + o];
    size_t hoff = ((size_t)(dd * 4 + l) * 1024 + b) * 512 + o;
    float it = 1.f / (1.f + expf(-zi));
    float ft = 1.f / (1.f + expf(-zf));
    float ot = 1.f / (1.f + expf(-zo));
    float ch = tanhf(zc);
    float st = (1.f / (1.f + expf(-zs))) * dw;
    float cn = ft * c[hoff] + it * ch * st;
    float hn = ot * tanhf(cn);
    c[hoff] = cn;
    h[hoff] = hn;
    if (l == 3) ycat[((size_t)b * 4 + ta) * 1024 + dd * 512 + o] = hn;
}

// ======================= tiny attention (N=4) =======================
template <int D>
__global__ void attn_kernel(const float* __restrict__ qkv, float* __restrict__ out, float scale) {
    int b = blockIdx.x, h = blockIdx.y, tid = threadIdx.x;
    float q[4], k[4], v[4];
    #pragma unroll
    for (int n = 0; n < 4; n++) {
        const float* base = qkv + (size_t)(b * 4 + n) * 3072 + h * D + tid;
        q[n] = base[0];
        k[n] = base[1024];
        v[n] = base[2048];
    }
    float p[16];
    #pragma unroll
    for (int n = 0; n < 4; n++)
        #pragma unroll
        for (int m = 0; m < 4; m++) p[n * 4 + m] = q[n] * k[m];
    #pragma unroll
    for (int off = 16; off > 0; off >>= 1)
        #pragma unroll
        for (int j = 0; j < 16; j++) p[j] += __shfl_down_sync(0xffffffffu, p[j], off);
    __shared__ float sp[16][8];
    int warp = tid >> 5, lane = tid & 31;
    if (lane == 0)
        #pragma unroll
        for (int j = 0; j < 16; j++) sp[j][warp] = p[j];
    __syncthreads();
    __shared__ float prob[16];
    if (tid < 4) {
        int n = tid;
        float s[4];
        #pragma unroll
        for (int m = 0; m < 4; m++) {
            float t = 0.f;
            #pragma unroll
            for (int w = 0; w < (D >> 5); w++) t += sp[n * 4 + m][w];
            s[m] = t * scale;
        }
        float mx = fmaxf(fmaxf(s[0], s[1]), fmaxf(s[2], s[3]));
        float e[4], sum = 0.f;
        #pragma unroll
        for (int m = 0; m < 4; m++) { e[m] = expf(s[m] - mx); sum += e[m]; }
        float inv = 1.f / sum;
        #pragma unroll
        for (int m = 0; m < 4; m++) prob[n * 4 + m] = e[m] * inv;
    }
    __syncthreads();
    #pragma unroll
    for (int n = 0; n < 4; n++) {
        float o = 0.f;
        #pragma unroll
        for (int m = 0; m < 4; m++) o += prob[n * 4 + m] * v[m];
        out[(size_t)(b * 4 + n) * 1024 + h * D + tid] = o;
    }
}

// ======================= final: gating + pwconv + fc =======================
__global__ void final_kernel(const float* __restrict__ y1, const float* __restrict__ zln,
                             const float* __restrict__ pw_w, const float* __restrict__ pw_b,
                             const float* __restrict__ fc_w, const float* __restrict__ fc_b,
                             float* __restrict__ out_fc, float* __restrict__ out_xf) {
    __shared__ float s[4][1024];
    __shared__ float xf[1024];
    __shared__ float sh[32];
    int b = blockIdx.x, tid = threadIdx.x;
    for (int i = tid; i < 4096; i += 256) {
        int t = i >> 10, j = i & 1023;
        float yv = y1 [(size_t)(b * 4 + t) * 1024 + j];
        float zv = zln[(size_t)(b * 4 + t) * 1024 + j];
        s[t][j] = yv * (1.f / (1.f + expf(-zv)));
    }
    __syncthreads();
    float w[12];
    #pragma unroll
    for (int i = 0; i < 12; i++) w[i] = pw_w[i];
    float pb = pw_b[0];
    for (int j = tid; j < 1024; j += 256) {
        float acc = pb;
        #pragma unroll
        for (int t = 0; t < 4; t++) {
            if (j > 0)    acc += w[t * 3 + 0] * s[t][j - 1];
                          acc += w[t * 3 + 1] * s[t][j];
            if (j < 1023) acc += w[t * 3 + 2] * s[t][j + 1];
        }
        xf[j] = acc;
        out_xf[(size_t)b * 1024 + j] = acc;
    }
    __syncthreads();
    float acc7[7] = {0.f, 0.f, 0.f, 0.f, 0.f, 0.f, 0.f};
    for (int j = tid; j < 1024; j += 256) {
        float xv = xf[j];
        #pragma unroll
        for (int o = 0; o < 7; o++) acc7[o] += xv * fc_w[o * 1024 + j];
    }
    for (int o = 0; o < 7; o++) {
        float r = blkSum(acc7[o], sh);
        if (tid == 0) out_fc[b * 7 + o] = r + fc_b[o];
    }
}

// ======================= host orchestration =======================
static void tgemm(const float* A, int lda, const float* B, int ldb, const float* bias,
                  float* C, int ldc, int M, int N, int K) {
    TGBatch tb;
    TG& p = tb.g[0];
    p.A1 = A; p.lda1 = lda; p.B1 = B; p.ldb1 = ldb; p.k1 = K;
    p.A2 = nullptr; p.lda2 = 0; p.B2 = nullptr; p.ldb2 = 0; p.k2 = 0;
    p.bias1 = bias; p.bias2 = nullptr;
    p.C = C; p.ldc = ldc;
    dim3 grid(N / 128, M / 128, 1);
    tgemm_kernel<<<grid, 256, TG_SMEM>>>(tb);
}

extern "C" void kernel_launch(void* const* d_in, const int* in_sizes, int n_in,
                              void* d_out, int out_size) {
    (void)in_sizes; (void)n_in;
    const float* x       = (const float*)d_in[0];
    const float* nv1     = (const float*)d_in[1];
    const float* nv2     = (const float*)d_in[2];
    const float* sc_w    = (const float*)d_in[3];
    const float* sc_b    = (const float*)d_in[4];
    const float* mp_w    = (const float*)d_in[5];
    const float* mp_b    = (const float*)d_in[6];
    const float* ec_w    = (const float*)d_in[7];
    const float* ec_b    = (const float*)d_in[8];
    const float* gbl_w   = (const float*)d_in[9];
    const float* gbl_b   = (const float*)d_in[10];
    const float* gbln_g  = (const float*)d_in[11];
    const float* gbln_b  = (const float*)d_in[12];
    const float* lstm_W  = (const float*)d_in[13];
    const float* lstm_Wb = (const float*)d_in[14];
    const float* lstm_U  = (const float*)d_in[15];
    const float* lstm_Ub = (const float*)d_in[16];
    const float* min_w   = (const float*)d_in[17];
    const float* min_b   = (const float*)d_in[18];
    const float* mout_w  = (const float*)d_in[19];
    const float* mout_b  = (const float*)d_in[20];
    const float* ln1_g   = (const float*)d_in[21];
    const float* ln1_b   = (const float*)d_in[22];
    const float* qkv_w   = (const float*)d_in[23];
    const float* dmin_g  = (const float*)d_in[24];
    const float* dmin_b  = (const float*)d_in[25];
    const float* pw_w    = (const float*)d_in[26];
    const float* pw_b    = (const float*)d_in[27];
    const float* fc_w    = (const float*)d_in[28];
    const float* fc_b    = (const float*)d_in[29];

    static bool init = false;
    static float *p_adj, *p_pqc, *p_xa, *p_oe, *p_gt, *p_xg, *p_gw, *p_h, *p_c, *p_z,
                 *p_ycat, *p_qkv, *p_att, *p_proj, *p_y1, *p_milz, *p_zln, *p_dfc, *p_dxf;
    if (!init) {
        void* t;
        cudaGetSymbolAddress(&t, g_adj);  p_adj  = (float*)t;
        cudaGetSymbolAddress(&t, g_pqc);  p_pqc  = (float*)t;
        cudaGetSymbolAddress(&t, g_xa);   p_xa   = (float*)t;
        cudaGetSymbolAddress(&t, g_oe);   p_oe   = (float*)t;
        cudaGetSymbolAddress(&t, g_gt);   p_gt   = (float*)t;
        cudaGetSymbolAddress(&t, g_xg);   p_xg   = (float*)t;
        cudaGetSymbolAddress(&t, g_gw);   p_gw   = (float*)t;
        cudaGetSymbolAddress(&t, g_h);    p_h    = (float*)t;
        cudaGetSymbolAddress(&t, g_c);    p_c    = (float*)t;
        cudaGetSymbolAddress(&t, g_z);    p_z    = (float*)t;
        cudaGetSymbolAddress(&t, g_ycat); p_ycat = (float*)t;
        cudaGetSymbolAddress(&t, g_qkv);  p_qkv  = (float*)t;
        cudaGetSymbolAddress(&t, g_att);  p_att  = (float*)t;
        cudaGetSymbolAddress(&t, g_proj); p_proj = (float*)t;
        cudaGetSymbolAddress(&t, g_y1);   p_y1   = (float*)t;
        cudaGetSymbolAddress(&t, g_milz); p_milz = (float*)t;
        cudaGetSymbolAddress(&t, g_zln);  p_zln  = (float*)t;
        cudaGetSymbolAddress(&t, g_dfc);  p_dfc  = (float*)t;
        cudaGetSymbolAddress(&t, g_dxf);  p_dxf  = (float*)t;
        cudaFuncSetAttribute(tgemm_kernel, cudaFuncAttributeMaxDynamicSharedMemorySize, TG_SMEM);
        init = true;
    }

    // ---- graph block ----
    adj_kernel<<<512, 128>>>(nv1, nv2, p_adj);
    pqc_kernel<<<1, 32>>>(mp_w, mp_b, sc_w, sc_b, p_pqc);
    tgemm(x, 512, p_adj, 512, nullptr, p_xa, 512, 4096, 512, 512);        // xa = X @ a^T
    graph_epi_kernel<<<2048, 256>>>(x, p_xa, ec_w, ec_b, p_pqc, p_oe);
    tgemm(p_oe, 512, gbl_w, 512, gbl_b, p_gt, 512, 4096, 512, 512);       // g = oe @ gbl_w^T
    lnsm_kernel<<<4096, 128>>>(x, p_gt, gbln_g, gbln_b, p_xg, p_gw);

    // ---- BiLSTM: wavefront over diagonals d = t + l; all cells on a diagonal
    //      (both directions) batched into ONE GEMM launch + ONE gate launch. ----
    cudaMemsetAsync(p_h, 0, sizeof(float) * 2 * 4 * 1024 * 512, 0);
    cudaMemsetAsync(p_c, 0, sizeof(float) * 2 * 4 * 1024 * 512, 0);
    for (int dph = 0; dph < 7; dph++) {
        TGBatch tb;
        GateMeta gm;
        int nc = 0;
        int l_lo = dph > 3 ? dph - 3 : 0;
        int l_hi = dph < 3 ? dph : 3;
        for (int dd = 0; dd < 2; dd++) {
            for (int l = l_lo; l <= l_hi; l++) {
                int t = dph - l;
                int ta = dd ? 3 - t : t;
                TG& p = tb.g[nc];
                p.A1 = (l == 0) ? (p_xg + ta * 512)
                                : (p_h + (size_t)(dd * 4 + (l - 1)) * 1024 * 512);
                p.lda1 = (l == 0) ? 2048 : 512;
                p.B1 = lstm_W + (size_t)(dd * 4 + l) * 5 * 512 * 512;
                p.ldb1 = 512;
                p.k1 = 512;
                p.A2 = p_h + (size_t)(dd * 4 + l) * 1024 * 512;
                p.lda2 = 512;
                p.B2 = lstm_U + (size_t)(dd * 4 + l) * 5 * 512 * 512;
                p.ldb2 = 512;
                p.k2 = 512;
                p.bias1 = lstm_Wb + (size_t)(dd * 4 + l) * 2560;
                p.bias2 = lstm_Ub + (size_t)(dd * 4 + l) * 2560;
                p.C = p_z + (size_t)nc * 1024 * 2560;
                p.ldc = 2560;
                gm.dir[nc] = dd; gm.lay[nc] = l; gm.tim[nc] = t;
                nc++;
            }
        }
        tgemm_kernel<<<dim3(20, 8, nc), 256, TG_SMEM>>>(tb);
        lstm_gate_wave<<<dim3(2048, nc), 256>>>(p_z, p_gw, p_h, p_c, p_ycat, gm);
    }

    // ---- MHA ----
    tgemm(p_ycat, 1024, min_w, 1024, min_b, p_qkv, 3072, 4096, 3072, 1024);
    attn_kernel<256><<<dim3(1024, 4), 256>>>(p_qkv, p_att, 1.f / 16.f);
    tgemm(p_att, 1024, mout_w, 1024, mout_b, p_proj, 1024, 4096, 1024, 1024);
    ln_kernel<<<4096, 256>>>(p_proj, ln1_g, ln1_b, p_y1);

    // ---- MIL attention ----
    tgemm(p_y1, 1024, qkv_w, 1024, nullptr, p_qkv, 3072, 4096, 3072, 1024);
    attn_kernel<128><<<dim3(1024, 8), 128>>>(p_qkv, p_milz, 0.08838834764831845f);
    ln_kernel<<<4096, 256>>>(p_milz, dmin_g, dmin_b, p_zln);

    // ---- gating + pwconv + fc ----
    float* out = (float*)d_out;
    float *ofc, *oxf;
    if (out_size >= 7168 + 1048576) { ofc = out; oxf = out + 7168; }
    else if (out_size == 7168)      { ofc = out; oxf = p_dxf; }
    else                            { oxf = out; ofc = p_dfc; }
    final_kernel<<<1024, 256>>>(p_y1, p_zln, pw_w, pw_b, fc_w, fc_b, ofc, oxf);
}

// round 8
// speedup vs baseline: 2.9897x; 1.1543x over previous
#include <cuda_runtime.h>
#include <math.h>
#include <stdint.h>

// ======================= scratch (static device memory) =======================
__device__ float g_adj [512*512];
__device__ float g_pqc [96];
__device__ float g_xa  [4096*512];
__device__ float g_oe  [4096*512];
__device__ float g_gt  [4096*512];
__device__ float g_xg  [4096*512];
__device__ float g_gw  [4096*512];
__device__ float g_h   [2*4*1024*512];
__device__ float g_c   [2*4*1024*512];
__device__ float g_z   [8*1024*2560];
__device__ float g_zx  [2*4096*2560];
__device__ float g_ycat[4096*1024];
__device__ float g_qkv [4096*3072];
__device__ float g_att [4096*1024];
__device__ float g_proj[4096*1024];
__device__ float g_y1  [4096*1024];
__device__ float g_milz[4096*1024];
__device__ float g_zln [4096*1024];
__device__ float g_dfc [1024*7];
__device__ float g_dxf [1024*1024];

// ======================= tf32 mma.sync GEMM: C = A1@B1^T [+ A2@B2^T] + bias =======================
// BM=128, BN=128, BK=32, 256 threads, warp tile 32x64, double-buffered smem.
// Batched: up to 8 independent GEMMs per launch via blockIdx.z. nt may be 0 (bias-only).
struct TG {
    const float *A1, *B1, *A2, *B2, *bias1, *bias2;
    float* C;
    int lda1, ldb1, lda2, ldb2, k1, k2, ldc;
};
struct TGBatch { TG g[8]; };

#define TG_SMEM 73728   // 2 stages * (128*36 A + 128*36 B) floats * 4B

__device__ __forceinline__ uint32_t f2tf(float x) {
    uint32_t r;
    asm("cvt.rna.tf32.f32 %0, %1;" : "=r"(r) : "f"(x));
    return r;
}

__device__ __forceinline__ void mma8(float* c, uint32_t a0, uint32_t a1, uint32_t a2, uint32_t a3,
                                     uint32_t b0, uint32_t b1) {
    asm volatile(
        "mma.sync.aligned.m16n8k8.row.col.f32.tf32.tf32.f32 "
        "{%0,%1,%2,%3},{%4,%5,%6,%7},{%8,%9},{%0,%1,%2,%3};"
        : "+f"(c[0]), "+f"(c[1]), "+f"(c[2]), "+f"(c[3])
        : "r"(a0), "r"(a1), "r"(a2), "r"(a3), "r"(b0), "r"(b1));
}

__global__ void __launch_bounds__(256, 2)
tgemm_kernel(TGBatch bat) {
    extern __shared__ float sm[];
    TG p = bat.g[blockIdx.z];
    const int tid = threadIdx.x, wid = tid >> 5, lane = tid & 31;
    const int wrow = wid & 3, wcol = wid >> 2;   // 4x2 warp grid, warp tile 32x64
    const int gid = lane >> 2, tig = lane & 3;
    const int bm = blockIdx.y * 128, bn = blockIdx.x * 128;
    const int nt1 = p.k1 >> 5, nt = nt1 + (p.k2 >> 5);
    const int lr = tid >> 1, lc = (tid & 1) * 16;

    float acc[16][4];
    #pragma unroll
    for (int i = 0; i < 16; i++)
        #pragma unroll
        for (int j = 0; j < 4; j++) acc[i][j] = 0.f;

    float4 ra[4], rb[4];

    auto ldg = [&](int it) {
        const float *Ap, *Bp;
        int lda, ldb, k0;
        if (it < nt1) { Ap = p.A1; lda = p.lda1; Bp = p.B1; ldb = p.ldb1; k0 = it * 32; }
        else          { Ap = p.A2; lda = p.lda2; Bp = p.B2; ldb = p.ldb2; k0 = (it - nt1) * 32; }
        const float* ar = Ap + (size_t)(bm + lr) * lda + k0 + lc;
        const float* br = Bp + (size_t)(bn + lr) * ldb + k0 + lc;
        #pragma unroll
        for (int i = 0; i < 4; i++) ra[i] = *(const float4*)(ar + 4 * i);
        #pragma unroll
        for (int i = 0; i < 4; i++) rb[i] = *(const float4*)(br + 4 * i);
    };

    auto sts = [&](int s) {
        uint32_t* A = (uint32_t*)sm + s * 9216 + lr * 36 + lc;
        uint32_t* B = A + 4608;
        #pragma unroll
        for (int i = 0; i < 4; i++) {
            uint4 v = make_uint4(f2tf(ra[i].x), f2tf(ra[i].y), f2tf(ra[i].z), f2tf(ra[i].w));
            *(uint4*)(A + 4 * i) = v;
        }
        #pragma unroll
        for (int i = 0; i < 4; i++) {
            uint4 v = make_uint4(f2tf(rb[i].x), f2tf(rb[i].y), f2tf(rb[i].z), f2tf(rb[i].w));
            *(uint4*)(B + 4 * i) = v;
        }
    };

    auto compute = [&](int s) {
        const uint32_t* A = (const uint32_t*)sm + s * 9216;
        const uint32_t* B = A + 4608;
        #pragma unroll
        for (int ks = 0; ks < 4; ks++) {
            int k = ks * 8 + tig;
            uint32_t af[2][4];
            #pragma unroll
            for (int mi = 0; mi < 2; mi++) {
                int r = wrow * 32 + mi * 16 + gid;
                af[mi][0] = A[r * 36 + k];
                af[mi][1] = A[(r + 8) * 36 + k];
                af[mi][2] = A[r * 36 + k + 4];
                af[mi][3] = A[(r + 8) * 36 + k + 4];
            }
            #pragma unroll
            for (int nj = 0; nj < 8; nj++) {
                int n = wcol * 64 + nj * 8 + gid;
                uint32_t b0 = B[n * 36 + k], b1 = B[n * 36 + k + 4];
                mma8(acc[nj],     af[0][0], af[0][1], af[0][2], af[0][3], b0, b1);
                mma8(acc[8 + nj], af[1][0], af[1][1], af[1][2], af[1][3], b0, b1);
            }
        }
    };

    if (nt > 0) {
        ldg(0);
        sts(0);
    }
    __syncthreads();
    for (int it = 0; it < nt; it++) {
        if (it + 1 < nt) ldg(it + 1);
        compute(it & 1);
        if (it + 1 < nt) sts((it + 1) & 1);
        __syncthreads();
    }

    // epilogue
    float2 bv[8];
    #pragma unroll
    for (int nj = 0; nj < 8; nj++) {
        int c = bn + wcol * 64 + nj * 8 + 2 * tig;
        float2 b = make_float2(0.f, 0.f);
        if (p.bias1) { float2 t = *(const float2*)(p.bias1 + c); b.x += t.x; b.y += t.y; }
        if (p.bias2) { float2 t = *(const float2*)(p.bias2 + c); b.x += t.x; b.y += t.y; }
        bv[nj] = b;
    }
    #pragma unroll
    for (int mi = 0; mi < 2; mi++) {
        int r0 = bm + wrow * 32 + mi * 16 + gid;
        #pragma unroll
        for (int nj = 0; nj < 8; nj++) {
            int c = bn + wcol * 64 + nj * 8 + 2 * tig;
            float* C0 = p.C + (size_t)r0 * p.ldc + c;
            float* C1 = p.C + (size_t)(r0 + 8) * p.ldc + c;
            *(float2*)C0 = make_float2(acc[mi * 8 + nj][0] + bv[nj].x, acc[mi * 8 + nj][1] + bv[nj].y);
            *(float2*)C1 = make_float2(acc[mi * 8 + nj][2] + bv[nj].x, acc[mi * 8 + nj][3] + bv[nj].y);
        }
    }
}

// ======================= block reduction helpers =======================
__device__ __forceinline__ float blkSum(float v, float* sh) {
    int tid = threadIdx.x;
    #pragma unroll
    for (int o = 16; o > 0; o >>= 1) v += __shfl_down_sync(0xffffffffu, v, o);
    __syncthreads();
    if ((tid & 31) == 0) sh[tid >> 5] = v;
    __syncthreads();
    if (tid < 32) {
        float x = (tid < ((int)blockDim.x >> 5)) ? sh[tid] : 0.f;
        #pragma unroll
        for (int o = 16; o > 0; o >>= 1) x += __shfl_down_sync(0xffffffffu, x, o);
        if (tid == 0) sh[0] = x;
    }
    __syncthreads();
    return sh[0];
}

__device__ __forceinline__ float blkMax(float v, float* sh) {
    int tid = threadIdx.x;
    #pragma unroll
    for (int o = 16; o > 0; o >>= 1) v = fmaxf(v, __shfl_down_sync(0xffffffffu, v, o));
    __syncthreads();
    if ((tid & 31) == 0) sh[tid >> 5] = v;
    __syncthreads();
    if (tid < 32) {
        float x = (tid < ((int)blockDim.x >> 5)) ? sh[tid] : -3.4e38f;
        #pragma unroll
        for (int o = 16; o > 0; o >>= 1) x = fmaxf(x, __shfl_down_sync(0xffffffffu, x, o));
        if (tid == 0) sh[0] = x;
    }
    __syncthreads();
    return sh[0];
}

// ======================= adjacency =======================
__global__ void adj_kernel(const float* __restrict__ nv1, const float* __restrict__ nv2,
                           float* __restrict__ a) {
    __shared__ float n1[32];
    __shared__ float row[512];
    __shared__ float sh[32];
    int v = blockIdx.x, tid = threadIdx.x;
    if (tid < 32) n1[tid] = nv1[v * 32 + tid];
    __syncthreads();
    float mx = -3.4e38f;
    #pragma unroll
    for (int i = 0; i < 4; i++) {
        int j = i * 128 + tid;
        float r = 0.f;
        #pragma unroll
        for (int k = 0; k < 32; k++) r += n1[k] * nv2[k * 512 + j];
        r = fmaxf(r, 0.f);
        row[j] = r;
        mx = fmaxf(mx, r);
    }
    mx = blkMax(mx, sh);
    float ssum = 0.f;
    #pragma unroll
    for (int i = 0; i < 4; i++) {
        int j = i * 128 + tid;
        float e = expf(row[j] - mx);
        row[j] = e;
        ssum += e;
    }
    ssum = blkSum(ssum, sh);
    float inv = 1.f / ssum;
    #pragma unroll
    for (int i = 0; i < 4; i++) {
        int j = i * 128 + tid;
        a[v * 512 + j] = (row[j] * inv + (j == v ? 1.f : 0.f)) * 0.5f;
    }
}

// ======================= P/Q/C precompute =======================
__global__ void pqc_kernel(const float* __restrict__ mp_w, const float* __restrict__ mp_b,
                           const float* __restrict__ sc_w, const float* __restrict__ sc_b,
                           float* __restrict__ pqc) {
    int o = threadIdx.x;
    float a1 = 0.f, a2 = 0.f, cc = 0.f;
    for (int c = 0; c < 32; c++) {
        float w1 = mp_w[o * 64 + c], w2 = mp_w[o * 64 + 32 + c];
        a1 += w1 * sc_w[c];
        a2 += w2 * sc_w[c];
        cc += (w1 + w2) * sc_b[c];
    }
    cc += mp_b[o];
    pqc[o]      = a1 + 0.7f * a2;
    pqc[32 + o] = 0.3f * a2;
    pqc[64 + o] = cc;
}

// ======================= graph epilogue =======================
__global__ void graph_epi_kernel(const float* __restrict__ x, const float* __restrict__ xa,
                                 const float* __restrict__ ecw, const float* __restrict__ ecb,
                                 const float* __restrict__ pqc, float* __restrict__ oe) {
    __shared__ float s_ec[512];
    __shared__ float s_pqc[96];
    __shared__ float s_ecb[4];
    int tid = threadIdx.x;
    for (int i = tid; i < 512; i += 256) s_ec[i] = ecw[i];
    if (tid < 96) s_pqc[tid] = pqc[tid];
    if (tid < 4) s_ecb[tid] = ecb[tid];
    __syncthreads();
    int idx = blockIdx.x * 256 + tid;
    int b = idx >> 9, v = idx & 511;
    float xv[4], xav[4];
    #pragma unroll
    for (int l = 0; l < 4; l++) {
        xv[l]  = x [(size_t)(b * 4 + l) * 512 + v];
        xav[l] = xa[(size_t)(b * 4 + l) * 512 + v];
    }
    float acc[4] = {s_ecb[0], s_ecb[1], s_ecb[2], s_ecb[3]};
    for (int c = 0; c < 32; c++) {
        float P = s_pqc[c], Q = s_pqc[32 + c], Cc = s_pqc[64 + c];
        #pragma unroll
        for (int l = 0; l < 4; l++) {
            float u = P * xv[l] + Q * xav[l] + Cc;
            float g = 0.5f * u * (1.f + erff(u * 0.70710678118654752f));
            #pragma unroll
            for (int o = 0; o < 4; o++) acc[o] += s_ec[o * 128 + c * 4 + l] * g;
        }
    }
    #pragma unroll
    for (int o = 0; o < 4; o++) oe[(size_t)(b * 4 + o) * 512 + v] = acc[o];
}

// ======================= LN(x+g) + softmax =======================
__global__ void lnsm_kernel(const float* __restrict__ x, const float* __restrict__ gt,
                            const float* __restrict__ gamma, const float* __restrict__ beta,
                            float* __restrict__ xg, float* __restrict__ gw) {
    __shared__ float sh[32];
    int r = blockIdx.x, tid = threadIdx.x;
    size_t off = (size_t)r * 512 + tid * 4;
    float4 a = *(const float4*)(x + off);
    float4 g = *(const float4*)(gt + off);
    float4 v = make_float4(a.x + g.x, a.y + g.y, a.z + g.z, a.w + g.w);
    float mean = blkSum(v.x + v.y + v.z + v.w, sh) * (1.f / 512.f);
    float4 d = make_float4(v.x - mean, v.y - mean, v.z - mean, v.w - mean);
    float var = blkSum(d.x * d.x + d.y * d.y + d.z * d.z + d.w * d.w, sh) * (1.f / 512.f);
    float inv = rsqrtf(var + 1e-5f);
    float4 gm = *(const float4*)(gamma + tid * 4);
    float4 bt = *(const float4*)(beta + tid * 4);
    float4 o = make_float4(d.x * inv * gm.x + bt.x, d.y * inv * gm.y + bt.y,
                           d.z * inv * gm.z + bt.z, d.w * inv * gm.w + bt.w);
    *(float4*)(xg + off) = o;
    float mx = blkMax(fmaxf(fmaxf(o.x, o.y), fmaxf(o.z, o.w)), sh);
    float4 e = make_float4(expf(o.x - mx), expf(o.y - mx), expf(o.z - mx), expf(o.w - mx));
    float s = blkSum(e.x + e.y + e.z + e.w, sh);
    float rs = 1.f / s;
    *(float4*)(gw + off) = make_float4(e.x * rs, e.y * rs, e.z * rs, e.w * rs);
}

// ======================= LN over 1024 =======================
__global__ void ln_kernel(const float* __restrict__ in, const float* __restrict__ gamma,
                          const float* __restrict__ beta, float* __restrict__ out) {
    __shared__ float sh[32];
    int r = blockIdx.x, tid = threadIdx.x;
    size_t off = (size_t)r * 1024 + tid * 4;
    float4 v = *(const float4*)(in + off);
    float mean = blkSum(v.x + v.y + v.z + v.w, sh) * (1.f / 1024.f);
    float4 d = make_float4(v.x - mean, v.y - mean, v.z - mean, v.w - mean);
    float var = blkSum(d.x * d.x + d.y * d.y + d.z * d.z + d.w * d.w, sh) * (1.f / 1024.f);
    float inv = rsqrtf(var + 1e-5f);
    float4 gm = *(const float4*)(gamma + tid * 4);
    float4 bt = *(const float4*)(beta + tid * 4);
    float4 o = make_float4(d.x * inv * gm.x + bt.x, d.y * inv * gm.y + bt.y,
                           d.z * inv * gm.z + bt.z, d.w * inv * gm.w + bt.w);
    *(float4*)(out + off) = o;
}

// ======================= LSTM gates (wavefront-batched, zx-hoisted, t0-skip) =======================
struct GateMeta { int dir[8], lay[8], tim[8], l0[8], t0[8]; };

__global__ void lstm_gate_wave(const float* __restrict__ z, const float* __restrict__ zx,
                               const float* __restrict__ gw,
                               float* __restrict__ h, float* __restrict__ c,
                               float* __restrict__ ycat, GateMeta gm) {
    int cell = blockIdx.y;
    int dd = gm.dir[cell], l = gm.lay[cell], t = gm.tim[cell];
    int idx = blockIdx.x * 256 + threadIdx.x;
    int b = idx >> 9, o = idx & 511;
    int ta = dd ? 3 - t : t;
    const float* zr = z + (size_t)cell * 1024 * 2560 + (size_t)b * 2560;
    float zi = zr[o], zf = zr[512 + o], zo = zr[1024 + o], zc = zr[1536 + o], zs = zr[2048 + o];
    if (gm.l0[cell]) {
        const float* zxr = zx + (size_t)dd * 4096 * 2560 + (size_t)(b * 4 + ta) * 2560;
        zi += zxr[o]; zf += zxr[512 + o]; zo += zxr[1024 + o];
        zc += zxr[1536 + o]; zs += zxr[2048 + o];
    }
    float dw = gw[(size_t)b * 2048 + ta * 512 + o];
    size_t hoff = ((size_t)(dd * 4 + l) * 1024 + b) * 512 + o;
    float cprev = gm.t0[cell] ? 0.f : c[hoff];
    float it = 1.f / (1.f + expf(-zi));
    float ft = 1.f / (1.f + expf(-zf));
    float ot = 1.f / (1.f + expf(-zo));
    float ch = tanhf(zc);
    float st = (1.f / (1.f + expf(-zs))) * dw;
    float cn = ft * cprev + it * ch * st;
    float hn = ot * tanhf(cn);
    c[hoff] = cn;
    h[hoff] = hn;
    if (l == 3) ycat[((size_t)b * 4 + ta) * 1024 + dd * 512 + o] = hn;
}

// ======================= tiny attention (N=4) =======================
template <int D>
__global__ void attn_kernel(const float* __restrict__ qkv, float* __restrict__ out, float scale) {
    int b = blockIdx.x, h = blockIdx.y, tid = threadIdx.x;
    float q[4], k[4], v[4];
    #pragma unroll
    for (int n = 0; n < 4; n++) {
        const float* base = qkv + (size_t)(b * 4 + n) * 3072 + h * D + tid;
        q[n] = base[0];
        k[n] = base[1024];
        v[n] = base[2048];
    }
    float p[16];
    #pragma unroll
    for (int n = 0; n < 4; n++)
        #pragma unroll
        for (int m = 0; m < 4; m++) p[n * 4 + m] = q[n] * k[m];
    #pragma unroll
    for (int off = 16; off > 0; off >>= 1)
        #pragma unroll
        for (int j = 0; j < 16; j++) p[j] += __shfl_down_sync(0xffffffffu, p[j], off);
    __shared__ float sp[16][8];
    int warp = tid >> 5, lane = tid & 31;
    if (lane == 0)
        #pragma unroll
        for (int j = 0; j < 16; j++) sp[j][warp] = p[j];
    __syncthreads();
    __shared__ float prob[16];
    if (tid < 4) {
        int n = tid;
        float s[4];
        #pragma unroll
        for (int m = 0; m < 4; m++) {
            float t = 0.f;
            #pragma unroll
            for (int w = 0; w < (D >> 5); w++) t += sp[n * 4 + m][w];
            s[m] = t * scale;
        }
        float mx = fmaxf(fmaxf(s[0], s[1]), fmaxf(s[2], s[3]));
        float e[4], sum = 0.f;
        #pragma unroll
        for (int m = 0; m < 4; m++) { e[m] = expf(s[m] - mx); sum += e[m]; }
        float inv = 1.f / sum;
        #pragma unroll
        for (int m = 0; m < 4; m++) prob[n * 4 + m] = e[m] * inv;
    }
    __syncthreads();
    #pragma unroll
    for (int n = 0; n < 4; n++) {
        float o = 0.f;
        #pragma unroll
        for (int m = 0; m < 4; m++) o += prob[n * 4 + m] * v[m];
        out[(size_t)(b * 4 + n) * 1024 + h * D + tid] = o;
    }
}

// ======================= final: gating + pwconv + fc =======================
__global__ void final_kernel(const float* __restrict__ y1, const float* __restrict__ zln,
                             const float* __restrict__ pw_w, const float* __restrict__ pw_b,
                             const float* __restrict__ fc_w, const float* __restrict__ fc_b,
                             float* __restrict__ out_fc, float* __restrict__ out_xf) {
    __shared__ float s[4][1024];
    __shared__ float xf[1024];
    __shared__ float sh[32];
    int b = blockIdx.x, tid = threadIdx.x;
    for (int i = tid; i < 4096; i += 256) {
        int t = i >> 10, j = i & 1023;
        float yv = y1 [(size_t)(b * 4 + t) * 1024 + j];
        float zv = zln[(size_t)(b * 4 + t) * 1024 + j];
        s[t][j] = yv * (1.f / (1.f + expf(-zv)));
    }
    __syncthreads();
    float w[12];
    #pragma unroll
    for (int i = 0; i < 12; i++) w[i] = pw_w[i];
    float pb = pw_b[0];
    for (int j = tid; j < 1024; j += 256) {
        float acc = pb;
        #pragma unroll
        for (int t = 0; t < 4; t++) {
            if (j > 0)    acc += w[t * 3 + 0] * s[t][j - 1];
                          acc += w[t * 3 + 1] * s[t][j];
            if (j < 1023) acc += w[t * 3 + 2] * s[t][j + 1];
        }
        xf[j] = acc;
        out_xf[(size_t)b * 1024 + j] = acc;
    }
    __syncthreads();
    float acc7[7] = {0.f, 0.f, 0.f, 0.f, 0.f, 0.f, 0.f};
    for (int j = tid; j < 1024; j += 256) {
        float xv = xf[j];
        #pragma unroll
        for (int o = 0; o < 7; o++) acc7[o] += xv * fc_w[o * 1024 + j];
    }
    for (int o = 0; o < 7; o++) {
        float r = blkSum(acc7[o], sh);
        if (tid == 0) out_fc[b * 7 + o] = r + fc_b[o];
    }
}

// ======================= host orchestration =======================
static void tgemm(const float* A, int lda, const float* B, int ldb, const float* bias,
                  float* C, int ldc, int M, int N, int K) {
    TGBatch tb;
    TG& p = tb.g[0];
    p.A1 = A; p.lda1 = lda; p.B1 = B; p.ldb1 = ldb; p.k1 = K;
    p.A2 = nullptr; p.lda2 = 0; p.B2 = nullptr; p.ldb2 = 0; p.k2 = 0;
    p.bias1 = bias; p.bias2 = nullptr;
    p.C = C; p.ldc = ldc;
    dim3 grid(N / 128, M / 128, 1);
    tgemm_kernel<<<grid, 256, TG_SMEM>>>(tb);
}

extern "C" void kernel_launch(void* const* d_in, const int* in_sizes, int n_in,
                              void* d_out, int out_size) {
    (void)in_sizes; (void)n_in;
    const float* x       = (const float*)d_in[0];
    const float* nv1     = (const float*)d_in[1];
    const float* nv2     = (const float*)d_in[2];
    const float* sc_w    = (const float*)d_in[3];
    const float* sc_b    = (const float*)d_in[4];
    const float* mp_w    = (const float*)d_in[5];
    const float* mp_b    = (const float*)d_in[6];
    const float* ec_w    = (const float*)d_in[7];
    const float* ec_b    = (const float*)d_in[8];
    const float* gbl_w   = (const float*)d_in[9];
    const float* gbl_b   = (const float*)d_in[10];
    const float* gbln_g  = (const float*)d_in[11];
    const float* gbln_b  = (const float*)d_in[12];
    const float* lstm_W  = (const float*)d_in[13];
    const float* lstm_Wb = (const float*)d_in[14];
    const float* lstm_U  = (const float*)d_in[15];
    const float* lstm_Ub = (const float*)d_in[16];
    const float* min_w   = (const float*)d_in[17];
    const float* min_b   = (const float*)d_in[18];
    const float* mout_w  = (const float*)d_in[19];
    const float* mout_b  = (const float*)d_in[20];
    const float* ln1_g   = (const float*)d_in[21];
    const float* ln1_b   = (const float*)d_in[22];
    const float* qkv_w   = (const float*)d_in[23];
    const float* dmin_g  = (const float*)d_in[24];
    const float* dmin_b  = (const float*)d_in[25];
    const float* pw_w    = (const float*)d_in[26];
    const float* pw_b    = (const float*)d_in[27];
    const float* fc_w    = (const float*)d_in[28];
    const float* fc_b    = (const float*)d_in[29];

    static bool init = false;
    static float *p_adj, *p_pqc, *p_xa, *p_oe, *p_gt, *p_xg, *p_gw, *p_h, *p_c, *p_z, *p_zx,
                 *p_ycat, *p_qkv, *p_att, *p_proj, *p_y1, *p_milz, *p_zln, *p_dfc, *p_dxf;
    if (!init) {
        void* t;
        cudaGetSymbolAddress(&t, g_adj);  p_adj  = (float*)t;
        cudaGetSymbolAddress(&t, g_pqc);  p_pqc  = (float*)t;
        cudaGetSymbolAddress(&t, g_xa);   p_xa   = (float*)t;
        cudaGetSymbolAddress(&t, g_oe);   p_oe   = (float*)t;
        cudaGetSymbolAddress(&t, g_gt);   p_gt   = (float*)t;
        cudaGetSymbolAddress(&t, g_xg);   p_xg   = (float*)t;
        cudaGetSymbolAddress(&t, g_gw);   p_gw   = (float*)t;
        cudaGetSymbolAddress(&t, g_h);    p_h    = (float*)t;
        cudaGetSymbolAddress(&t, g_c);    p_c    = (float*)t;
        cudaGetSymbolAddress(&t, g_z);    p_z    = (float*)t;
        cudaGetSymbolAddress(&t, g_zx);   p_zx   = (float*)t;
        cudaGetSymbolAddress(&t, g_ycat); p_ycat = (float*)t;
        cudaGetSymbolAddress(&t, g_qkv);  p_qkv  = (float*)t;
        cudaGetSymbolAddress(&t, g_att);  p_att  = (float*)t;
        cudaGetSymbolAddress(&t, g_proj); p_proj = (float*)t;
        cudaGetSymbolAddress(&t, g_y1);   p_y1   = (float*)t;
        cudaGetSymbolAddress(&t, g_milz); p_milz = (float*)t;
        cudaGetSymbolAddress(&t, g_zln);  p_zln  = (float*)t;
        cudaGetSymbolAddress(&t, g_dfc);  p_dfc  = (float*)t;
        cudaGetSymbolAddress(&t, g_dxf);  p_dxf  = (float*)t;
        cudaFuncSetAttribute(tgemm_kernel, cudaFuncAttributeMaxDynamicSharedMemorySize, TG_SMEM);
        init = true;
    }

    // ---- graph block ----
    adj_kernel<<<512, 128>>>(nv1, nv2, p_adj);
    pqc_kernel<<<1, 32>>>(mp_w, mp_b, sc_w, sc_b, p_pqc);
    tgemm(x, 512, p_adj, 512, nullptr, p_xa, 512, 4096, 512, 512);        // xa = X @ a^T
    graph_epi_kernel<<<2048, 256>>>(x, p_xa, ec_w, ec_b, p_pqc, p_oe);
    tgemm(p_oe, 512, gbl_w, 512, gbl_b, p_gt, 512, 4096, 512, 512);       // g = oe @ gbl_w^T
    lnsm_kernel<<<4096, 128>>>(x, p_gt, gbln_g, gbln_b, p_xg, p_gw);

    // ---- BiLSTM ----
    // upfront: zx[d] = xg @ W[d,0]^T + Wb  (all 4 timesteps at once, both dirs, parallel)
    {
        TGBatch tb;
        for (int dd = 0; dd < 2; dd++) {
            TG& q = tb.g[dd];
            q.A1 = p_xg; q.lda1 = 512;
            q.B1 = lstm_W + (size_t)(dd * 4) * 5 * 512 * 512; q.ldb1 = 512; q.k1 = 512;
            q.A2 = nullptr; q.lda2 = 0; q.B2 = nullptr; q.ldb2 = 0; q.k2 = 0;
            q.bias1 = lstm_Wb + (size_t)(dd * 4) * 2560; q.bias2 = nullptr;
            q.C = p_zx + (size_t)dd * 4096 * 2560; q.ldc = 2560;
        }
        tgemm_kernel<<<dim3(20, 32, 2), 256, TG_SMEM>>>(tb);
    }
    // wavefront over diagonals dph = t + l; l=0 input term hoisted; t=0 U-term skipped (exact)
    for (int dph = 0; dph < 7; dph++) {
        TGBatch tb;
        GateMeta gm;
        int nc = 0;
        int l_lo = dph > 3 ? dph - 3 : 0;
        int l_hi = dph < 3 ? dph : 3;
        for (int dd = 0; dd < 2; dd++) {
            for (int l = l_lo; l <= l_hi; l++) {
                int t = dph - l;
                TG& p = tb.g[nc];
                if (l > 0) {
                    p.A1 = p_h + (size_t)(dd * 4 + (l - 1)) * 1024 * 512; p.lda1 = 512;
                    p.B1 = lstm_W + (size_t)(dd * 4 + l) * 5 * 512 * 512; p.ldb1 = 512;
                    p.k1 = 512;
                    p.bias1 = lstm_Wb + (size_t)(dd * 4 + l) * 2560;
                } else {
                    p.A1 = nullptr; p.lda1 = 0; p.B1 = nullptr; p.ldb1 = 0; p.k1 = 0;
                    p.bias1 = nullptr;   // Wb folded into zx
                }
                if (t > 0) {
                    p.A2 = p_h + (size_t)(dd * 4 + l) * 1024 * 512; p.lda2 = 512;
                    p.B2 = lstm_U + (size_t)(dd * 4 + l) * 5 * 512 * 512; p.ldb2 = 512;
                    p.k2 = 512;
                } else {
                    p.A2 = nullptr; p.lda2 = 0; p.B2 = nullptr; p.ldb2 = 0; p.k2 = 0;
                }
                p.bias2 = lstm_Ub + (size_t)(dd * 4 + l) * 2560;
                p.C = p_z + (size_t)nc * 1024 * 2560; p.ldc = 2560;
                gm.dir[nc] = dd; gm.lay[nc] = l; gm.tim[nc] = t;
                gm.l0[nc] = (l == 0); gm.t0[nc] = (t == 0);
                nc++;
            }
        }
        tgemm_kernel<<<dim3(20, 8, nc), 256, TG_SMEM>>>(tb);
        lstm_gate_wave<<<dim3(2048, nc), 256>>>(p_z, p_zx, p_gw, p_h, p_c, p_ycat, gm);
    }

    // ---- MHA ----
    tgemm(p_ycat, 1024, min_w, 1024, min_b, p_qkv, 3072, 4096, 3072, 1024);
    attn_kernel<256><<<dim3(1024, 4), 256>>>(p_qkv, p_att, 1.f / 16.f);
    tgemm(p_att, 1024, mout_w, 1024, mout_b, p_proj, 1024, 4096, 1024, 1024);
    ln_kernel<<<4096, 256>>>(p_proj, ln1_g, ln1_b, p_y1);

    // ---- MIL attention ----
    tgemm(p_y1, 1024, qkv_w, 1024, nullptr, p_qkv, 3072, 4096, 3072, 1024);
    attn_kernel<128><<<dim3(1024, 8), 128>>>(p_qkv, p_milz, 0.08838834764831845f);
    ln_kernel<<<4096, 256>>>(p_milz, dmin_g, dmin_b, p_zln);

    // ---- gating + pwconv + fc ----
    float* out = (float*)d_out;
    float *ofc, *oxf;
    if (out_size >= 7168 + 1048576) { ofc = out; oxf = out + 7168; }
    else if (out_size == 7168)      { ofc = out; oxf = p_dxf; }
    else                            { oxf = out; ofc = p_dfc; }
    final_kernel<<<1024, 256>>>(p_y1, p_zln, pw_w, pw_b, fc_w, fc_b, ofc, oxf);
}